// round 10
// baseline (speedup 1.0000x reference)
#include <cuda_runtime.h>
#include <cuda_fp16.h>
#include <mma.h>
#include <math.h>

using namespace nvcuda;

#define N_NODES 50000
#define N_EDGES 1600000
#define E_TOT   (N_EDGES + N_NODES)
#define HID     128
#define IND     13
#define OUTD    5
#define SCAN_BS 512
#define NBLK    ((N_NODES + SCAN_BS - 1) / SCAN_BS)   // 98

// ---------------- scratch (static device globals; no allocation) ----------------
__device__ int      g_ssrc[E_TOT];           // CSR-sorted source indices (by dst)
__device__ int      g_cnt[N_NODES];
__device__ int      g_off[N_NODES + 1];
__device__ int      g_cur[N_NODES];
__device__ int      g_bsum[NBLK];
__device__ unsigned g_maxas[3];              // per-layer global max of a_src·h (encoded)
__device__ __align__(16) __half g_hh[N_NODES * HID];    // transformed features, fp16
__device__ __align__(16) __half g_feath[N_NODES * HID]; // layer input, fp16
__device__ __align__(16) __half g_W2h[HID * HID];       // W2 in fp16
__device__ float    g_as[N_NODES];
__device__ float    g_ad[N_NODES];
__device__ float    g_h5[N_NODES * OUTD];

// order-preserving float<->uint encoding (atomicMax-able, order-invariant => deterministic)
__device__ __forceinline__ unsigned enc_f(float f) {
    unsigned u = __float_as_uint(f);
    return (u >> 31) ? ~u : (u | 0x80000000u);
}
__device__ __forceinline__ float dec_f(unsigned e) {
    return __uint_as_float((e >> 31) ? (e ^ 0x80000000u) : ~e);
}
__device__ __forceinline__ float leaky(float e) { return e > 0.f ? e : 0.2f * e; }

// ---------------- CSR build ----------------
__global__ void k_zero_cnt() {
    int i = blockIdx.x * blockDim.x + threadIdx.x;
    if (i < N_NODES) g_cnt[i] = 0;
}

__global__ void k_hist(const int* __restrict__ ei) {
    int e = blockIdx.x * blockDim.x + threadIdx.x;
    if (e >= E_TOT) return;
    int d = (e < N_EDGES) ? ei[N_EDGES + e] : e - N_EDGES;   // int32 (JAX x64 disabled)
    atomicAdd(&g_cnt[d], 1);
}

__global__ void k_blocksum() {
    __shared__ int sm[SCAN_BS];
    int i = blockIdx.x * SCAN_BS + threadIdx.x;
    sm[threadIdx.x] = (i < N_NODES) ? g_cnt[i] : 0;
    __syncthreads();
    for (int o = SCAN_BS / 2; o > 0; o >>= 1) {
        if (threadIdx.x < o) sm[threadIdx.x] += sm[threadIdx.x + o];
        __syncthreads();
    }
    if (threadIdx.x == 0) {
        g_bsum[blockIdx.x] = sm[0];
        if (blockIdx.x == 0) { g_maxas[0] = 0u; g_maxas[1] = 0u; g_maxas[2] = 0u; }
    }
}

// offsets: intra-block Hillis-Steele scan + on-the-fly block prefix from raw g_bsum
__global__ void k_offsets() {
    __shared__ int sm[SCAN_BS];
    __shared__ int sb[128];
    int t = threadIdx.x;
    int i = blockIdx.x * SCAN_BS + t;
    int v = (i < N_NODES) ? g_cnt[i] : 0;
    sm[t] = v;
    if (t < 128) {
        int bv = (t < NBLK && t < blockIdx.x) ? g_bsum[t] : 0;
        sb[t] = bv;
    }
    __syncthreads();
    // reduce sb -> block prefix
    for (int o = 64; o > 0; o >>= 1) {
        if (t < o) sb[t] += sb[t + o];
        __syncthreads();
    }
    // inclusive scan of sm
    for (int o = 1; o < SCAN_BS; o <<= 1) {
        int u = (t >= o) ? sm[t - o] : 0;
        __syncthreads();
        sm[t] += u;
        __syncthreads();
    }
    if (i < N_NODES) {
        int excl = sm[t] - v + sb[0];
        g_off[i] = excl;
        g_cur[i] = excl;
        if (i == N_NODES - 1) g_off[N_NODES] = excl + v;   // == E_TOT
    }
}

__global__ void k_fill(const int* __restrict__ ei) {
    int e = blockIdx.x * blockDim.x + threadIdx.x;
    if (e >= E_TOT) return;
    int s, d;
    if (e < N_EDGES) { s = ei[e]; d = ei[N_EDGES + e]; }
    else             { s = d = e - N_EDGES; }
    int pos = atomicAdd(&g_cur[d], 1);
    g_ssrc[pos] = s;
}

// ---------------- helpers ----------------
__device__ __forceinline__ uint2 pack_half4(float a, float b, float c, float d) {
    __half2 h0 = __float22half2_rn(make_float2(a, b));
    __half2 h1 = __float22half2_rn(make_float2(c, d));
    uint2 u;
    u.x = *reinterpret_cast<unsigned*>(&h0);
    u.y = *reinterpret_cast<unsigned*>(&h1);
    return u;
}
__device__ __forceinline__ float4 unpack_half4(uint2 u) {
    __half2 h0 = *reinterpret_cast<__half2*>(&u.x);
    __half2 h1 = *reinterpret_cast<__half2*>(&u.y);
    float2 f0 = __half22float2(h0), f1 = __half22float2(h1);
    return make_float4(f0.x, f0.y, f1.x, f1.y);
}

// ---------------- layer 1 GEMM (K=13) + fused attention dots + global max ---------
__global__ void k_gemm1(const float* __restrict__ x, const float* __restrict__ W1,
                        const float* __restrict__ a_src, const float* __restrict__ a_dst) {
    __shared__ __align__(16) float Ws[IND * HID];
    __shared__ __align__(16) float As[HID];
    __shared__ __align__(16) float Ad[HID];
    for (int i = threadIdx.x; i < IND * HID; i += blockDim.x) Ws[i] = W1[i];
    for (int i = threadIdx.x; i < HID; i += blockDim.x) { As[i] = a_src[i]; Ad[i] = a_dst[i]; }
    __syncthreads();
    int warp = threadIdx.x >> 5, lane = threadIdx.x & 31;
    int node = blockIdx.x * 8 + warp;
    if (node >= N_NODES) return;
    float xv[IND];
#pragma unroll
    for (int k = 0; k < IND; ++k) xv[k] = x[node * IND + k];
    float4 acc = {0.f, 0.f, 0.f, 0.f};
#pragma unroll
    for (int k = 0; k < IND; ++k) {
        float4 w = *(const float4*)&Ws[k * HID + lane * 4];
        acc.x += xv[k] * w.x; acc.y += xv[k] * w.y;
        acc.z += xv[k] * w.z; acc.w += xv[k] * w.w;
    }
    ((uint2*)g_hh)[node * 32 + lane] = pack_half4(acc.x, acc.y, acc.z, acc.w);
    float4 a1 = *(const float4*)&As[lane * 4];
    float4 a2 = *(const float4*)&Ad[lane * 4];
    float s1 = acc.x * a1.x + acc.y * a1.y + acc.z * a1.z + acc.w * a1.w;
    float s2 = acc.x * a2.x + acc.y * a2.y + acc.z * a2.z + acc.w * a2.w;
#pragma unroll
    for (int o = 16; o; o >>= 1) {
        s1 += __shfl_xor_sync(0xffffffffu, s1, o);
        s2 += __shfl_xor_sync(0xffffffffu, s2, o);
    }
    if (lane == 0) {
        g_as[node] = s1; g_ad[node] = s2;
        atomicMax(&g_maxas[0], enc_f(s1));
    }
}

// ---------------- W2 -> fp16 ----------------
__global__ void k_cvtW2(const float* __restrict__ W) {
    int i = blockIdx.x * blockDim.x + threadIdx.x;
    if (i < HID * HID) g_W2h[i] = __float2half(W[i]);
}

// ---------------- layer 2 GEMM via WMMA: 64 rows x 128 cols per block ----------
#define FS_LD 136
__global__ void k_gemm2_wmma() {
    __shared__ __align__(16) __half Fs[64 * FS_LD];
    __shared__ __align__(16) float  Os[8 * 256];       // per-warp 16x16 staging
    int rowBase = blockIdx.x * 64;
    int warp = threadIdx.x >> 5, lane = threadIdx.x & 31;
    for (int v = threadIdx.x * 8; v < 64 * HID; v += 256 * 8) {
        int r = v >> 7, c = v & 127;
        int gr = rowBase + r;
        uint4 d = (gr < N_NODES) ? *(const uint4*)&g_feath[gr * HID + c]
                                 : make_uint4(0u, 0u, 0u, 0u);
        *(uint4*)&Fs[r * FS_LD + c] = d;
    }
    __syncthreads();
    int rowTile = warp >> 1;
    int colTile0 = (warp & 1) * 4;
    wmma::fragment<wmma::accumulator, 16, 16, 16, float> acc[4];
#pragma unroll
    for (int t = 0; t < 4; ++t) wmma::fill_fragment(acc[t], 0.f);
    for (int k = 0; k < HID; k += 16) {
        wmma::fragment<wmma::matrix_a, 16, 16, 16, __half, wmma::row_major> a;
        wmma::load_matrix_sync(a, &Fs[rowTile * 16 * FS_LD + k], FS_LD);
#pragma unroll
        for (int t = 0; t < 4; ++t) {
            wmma::fragment<wmma::matrix_b, 16, 16, 16, __half, wmma::row_major> b;
            wmma::load_matrix_sync(b, &g_W2h[k * HID + (colTile0 + t) * 16], HID);
            wmma::mma_sync(acc[t], a, b, acc[t]);
        }
    }
    float* os = &Os[warp * 256];
#pragma unroll
    for (int t = 0; t < 4; ++t) {
        wmma::store_matrix_sync(os, acc[t], 16, wmma::mem_row_major);
        __syncwarp();
        int r = lane >> 1, c8 = (lane & 1) * 8;
        int gr = rowBase + rowTile * 16 + r;
        if (gr < N_NODES) {
            int gc = (colTile0 + t) * 16 + c8;
            const float* p = &os[r * 16 + c8];
            __half2* dst = (__half2*)&g_hh[gr * HID + gc];
#pragma unroll
            for (int q = 0; q < 4; ++q)
                dst[q] = __float22half2_rn(make_float2(p[2 * q], p[2 * q + 1]));
        }
        __syncwarp();
    }
}

// attention dots for layer 2 (h row . a_src / a_dst), h in fp16; + global max
__global__ void k_rowdot(const float* __restrict__ a_src, const float* __restrict__ a_dst) {
    int warp = threadIdx.x >> 5, lane = threadIdx.x & 31;
    int node = blockIdx.x * 8 + warp;
    if (node >= N_NODES) return;
    float4 hv = unpack_half4(((const uint2*)g_hh)[node * 32 + lane]);
    float4 a1 = make_float4(a_src[lane * 4], a_src[lane * 4 + 1], a_src[lane * 4 + 2], a_src[lane * 4 + 3]);
    float4 a2 = make_float4(a_dst[lane * 4], a_dst[lane * 4 + 1], a_dst[lane * 4 + 2], a_dst[lane * 4 + 3]);
    float s1 = hv.x * a1.x + hv.y * a1.y + hv.z * a1.z + hv.w * a1.w;
    float s2 = hv.x * a2.x + hv.y * a2.y + hv.z * a2.z + hv.w * a2.w;
#pragma unroll
    for (int o = 16; o; o >>= 1) {
        s1 += __shfl_xor_sync(0xffffffffu, s1, o);
        s2 += __shfl_xor_sync(0xffffffffu, s2, o);
    }
    if (lane == 0) {
        g_as[node] = s1; g_ad[node] = s2;
        atomicMax(&g_maxas[1], enc_f(s1));
    }
}

// ---------------- fused softmax-aggregation, F=128 (warp per node, fp16 gather) ----
// single edge pass: shift = leaky(global_max(as) + ad_i) >= all e_ij (softmax invariant)
__global__ void k_agg128(const float* __restrict__ b, int layer) {
    int warp = threadIdx.x >> 5, lane = threadIdx.x & 31;
    int i = blockIdx.x * 8 + warp;
    if (i >= N_NODES) return;
    int start = g_off[i], end = g_off[i + 1];
    float adi = g_ad[i];
    float m = leaky(dec_f(g_maxas[layer]) + adi);
    float4 acc = {0.f, 0.f, 0.f, 0.f};
    float denom = 0.f;
    const uint2* hh = (const uint2*)g_hh;
    int j = start;
    for (; j + 4 <= end; j += 4) {
        int s0 = g_ssrc[j], s1 = g_ssrc[j + 1], s2 = g_ssrc[j + 2], s3 = g_ssrc[j + 3];
        float e0 = g_as[s0] + adi, e1 = g_as[s1] + adi,
              e2 = g_as[s2] + adi, e3 = g_as[s3] + adi;
        uint2 p0 = hh[s0 * 32 + lane], p1 = hh[s1 * 32 + lane],
              p2 = hh[s2 * 32 + lane], p3 = hh[s3 * 32 + lane];
        float x0 = __expf(leaky(e0) - m), x1 = __expf(leaky(e1) - m),
              x2 = __expf(leaky(e2) - m), x3 = __expf(leaky(e3) - m);
        denom += (x0 + x1) + (x2 + x3);
        float4 h0 = unpack_half4(p0), h1 = unpack_half4(p1),
               h2 = unpack_half4(p2), h3 = unpack_half4(p3);
        acc.x += x0 * h0.x + x1 * h1.x + x2 * h2.x + x3 * h3.x;
        acc.y += x0 * h0.y + x1 * h1.y + x2 * h2.y + x3 * h3.y;
        acc.z += x0 * h0.z + x1 * h1.z + x2 * h2.z + x3 * h3.z;
        acc.w += x0 * h0.w + x1 * h1.w + x2 * h2.w + x3 * h3.w;
    }
    for (; j < end; ++j) {
        int s = g_ssrc[j];
        float ex = __expf(leaky(g_as[s] + adi) - m);
        denom += ex;
        float4 hv = unpack_half4(hh[s * 32 + lane]);
        acc.x += ex * hv.x; acc.y += ex * hv.y;
        acc.z += ex * hv.z; acc.w += ex * hv.w;
    }
    float inv = 1.f / (denom + 1e-16f);
    float4 bv = make_float4(b[lane * 4], b[lane * 4 + 1], b[lane * 4 + 2], b[lane * 4 + 3]);
    float4 r;
    r.x = fmaxf(acc.x * inv + bv.x, 0.f); r.y = fmaxf(acc.y * inv + bv.y, 0.f);
    r.z = fmaxf(acc.z * inv + bv.z, 0.f); r.w = fmaxf(acc.w * inv + bv.w, 0.f);
    ((uint2*)g_feath)[i * 32 + lane] = pack_half4(r.x, r.y, r.z, r.w);
}

// ---------------- layer 3 GEMM (K=128 -> 5, fp16 input) + attention dots + max ----
__global__ void k_gemm3(const float* __restrict__ W3,
                        const float* __restrict__ a_src, const float* __restrict__ a_dst) {
    __shared__ float Ws[HID * OUTD];
    __shared__ float As[OUTD], Ad[OUTD];
    for (int i = threadIdx.x; i < HID * OUTD; i += blockDim.x) Ws[i] = W3[i];
    if (threadIdx.x < OUTD) { As[threadIdx.x] = a_src[threadIdx.x]; Ad[threadIdx.x] = a_dst[threadIdx.x]; }
    __syncthreads();
    int warp = threadIdx.x >> 5, lane = threadIdx.x & 31;
    int node = blockIdx.x * 8 + warp;
    if (node >= N_NODES) return;
    float4 f = unpack_half4(((const uint2*)g_feath)[node * 32 + lane]);
    int k0 = lane * 4;
    float hc[OUTD];
#pragma unroll
    for (int c = 0; c < OUTD; ++c) {
        float s = f.x * Ws[(k0 + 0) * OUTD + c] + f.y * Ws[(k0 + 1) * OUTD + c]
                + f.z * Ws[(k0 + 2) * OUTD + c] + f.w * Ws[(k0 + 3) * OUTD + c];
#pragma unroll
        for (int o = 16; o; o >>= 1) s += __shfl_xor_sync(0xffffffffu, s, o);
        hc[c] = s;
    }
    if (lane == 0) {
        float s1 = 0.f, s2 = 0.f;
#pragma unroll
        for (int c = 0; c < OUTD; ++c) {
            g_h5[node * OUTD + c] = hc[c];
            s1 += hc[c] * As[c];
            s2 += hc[c] * Ad[c];
        }
        g_as[node] = s1; g_ad[node] = s2;
        atomicMax(&g_maxas[2], enc_f(s1));
    }
}

// ---------------- fused aggregation F=5 + bias + log_softmax (warp per node) -------
__global__ void k_agg5(const float* __restrict__ b3, float* __restrict__ out) {
    int warp = threadIdx.x >> 5, lane = threadIdx.x & 31;
    int i = blockIdx.x * 8 + warp;
    if (i >= N_NODES) return;
    int start = g_off[i], end = g_off[i + 1];
    float adi = g_ad[i];
    float m = leaky(dec_f(g_maxas[2]) + adi);
    float a0 = 0.f, a1 = 0.f, a2 = 0.f, a3 = 0.f, a4 = 0.f, denom = 0.f;
    for (int j = start + lane; j < end; j += 32) {
        int s = g_ssrc[j];
        float ex = __expf(leaky(g_as[s] + adi) - m);
        denom += ex;
        const float* hp = &g_h5[s * OUTD];
        a0 += ex * hp[0]; a1 += ex * hp[1]; a2 += ex * hp[2];
        a3 += ex * hp[3]; a4 += ex * hp[4];
    }
#pragma unroll
    for (int o = 16; o; o >>= 1) {
        denom += __shfl_xor_sync(0xffffffffu, denom, o);
        a0 += __shfl_xor_sync(0xffffffffu, a0, o);
        a1 += __shfl_xor_sync(0xffffffffu, a1, o);
        a2 += __shfl_xor_sync(0xffffffffu, a2, o);
        a3 += __shfl_xor_sync(0xffffffffu, a3, o);
        a4 += __shfl_xor_sync(0xffffffffu, a4, o);
    }
    if (lane == 0) {
        float inv = 1.f / (denom + 1e-16f);
        float v[OUTD] = {a0 * inv + b3[0], a1 * inv + b3[1], a2 * inv + b3[2],
                         a3 * inv + b3[3], a4 * inv + b3[4]};
        float mx = -1e30f;
#pragma unroll
        for (int c = 0; c < OUTD; ++c) mx = fmaxf(mx, v[c]);
        float se = 0.f;
#pragma unroll
        for (int c = 0; c < OUTD; ++c) se += __expf(v[c] - mx);
        float lse = mx + logf(se);
#pragma unroll
        for (int c = 0; c < OUTD; ++c) out[i * OUTD + c] = v[c] - lse;
    }
}

// ---------------- launch ----------------
extern "C" void kernel_launch(void* const* d_in, const int* in_sizes, int n_in,
                              void* d_out, int out_size) {
    const float* x   = (const float*)d_in[0];
    const int*   ei  = (const int*)d_in[1];       // int32: JAX x64 is disabled
    const float* W1  = (const float*)d_in[2];
    const float* as1 = (const float*)d_in[3];
    const float* ad1 = (const float*)d_in[4];
    const float* b1  = (const float*)d_in[5];
    const float* W2  = (const float*)d_in[6];
    const float* as2 = (const float*)d_in[7];
    const float* ad2 = (const float*)d_in[8];
    const float* b2  = (const float*)d_in[9];
    const float* W3  = (const float*)d_in[10];
    const float* as3 = (const float*)d_in[11];
    const float* ad3 = (const float*)d_in[12];
    const float* b3  = (const float*)d_in[13];
    float* out = (float*)d_out;

    // CSR build (shared by all 3 layers; rebuilt every call — no caching)
    k_zero_cnt<<<(N_NODES + 255) / 256, 256>>>();
    k_hist<<<(E_TOT + 255) / 256, 256>>>(ei);
    k_blocksum<<<NBLK, SCAN_BS>>>();
    k_offsets<<<NBLK, SCAN_BS>>>();
    k_fill<<<(E_TOT + 255) / 256, 256>>>(ei);

    int nwb = (N_NODES + 7) / 8;   // warp-per-node grids

    // layer 1 (+ W2 conversion, independent)
    k_cvtW2<<<(HID * HID + 255) / 256, 256>>>(W2);
    k_gemm1<<<nwb, 256>>>(x, W1, as1, ad1);
    k_agg128<<<nwb, 256>>>(b1, 0);
    // layer 2
    k_gemm2_wmma<<<(N_NODES + 63) / 64, 256>>>();
    k_rowdot<<<nwb, 256>>>(as2, ad2);
    k_agg128<<<nwb, 256>>>(b2, 1);
    // layer 3
    k_gemm3<<<nwb, 256>>>(W3, as3, ad3);
    k_agg5<<<nwb, 256>>>(b3, out);
}

// round 11
// speedup vs baseline: 1.2201x; 1.2201x over previous
#include <cuda_runtime.h>
#include <cuda_fp16.h>
#include <mma.h>
#include <math.h>

using namespace nvcuda;

#define N_NODES 50000
#define N_EDGES 1600000
#define E_TOT   (N_EDGES + N_NODES)
#define HID     128
#define IND     13
#define OUTD    5
#define SCAN_BS 512
#define NBLK    ((N_NODES + SCAN_BS - 1) / SCAN_BS)   // 98

// ---------------- scratch (static device globals; no allocation) ----------------
__device__ int      g_ssrc[E_TOT];           // CSR-sorted source indices (by dst)
__device__ int      g_cnt[N_NODES];
__device__ int      g_off[N_NODES + 1];
__device__ int      g_cur[N_NODES];
__device__ int      g_bsum[NBLK];
__device__ unsigned g_maxas[3];              // per-layer global max of a_src·h (encoded)
__device__ __align__(16) __half g_hh[N_NODES * HID];    // transformed features, fp16
__device__ __align__(16) __half g_feath[N_NODES * HID]; // layer input, fp16
__device__ __align__(16) __half g_W2h[HID * HID];       // W2 in fp16
__device__ float    g_as[N_NODES];
__device__ float    g_ad[N_NODES];
__device__ float    g_h5[N_NODES * OUTD];

// order-preserving float<->uint encoding (atomicMax-able, order-invariant => deterministic)
__device__ __forceinline__ unsigned enc_f(float f) {
    unsigned u = __float_as_uint(f);
    return (u >> 31) ? ~u : (u | 0x80000000u);
}
__device__ __forceinline__ float dec_f(unsigned e) {
    return __uint_as_float((e >> 31) ? (e ^ 0x80000000u) : ~e);
}
__device__ __forceinline__ float leaky(float e) { return e > 0.f ? e : 0.2f * e; }

// block-level (8 warps) max reduce then ONE atomic per block
__device__ __forceinline__ void block_atomic_max(unsigned* dst, float s1, int warp, int lane,
                                                 float* smax) {
    if (lane == 0) smax[warp] = s1;
    __syncthreads();
    if (threadIdx.x == 0) {
        float m = smax[0];
#pragma unroll
        for (int w = 1; w < 8; ++w) m = fmaxf(m, smax[w]);
        atomicMax(dst, enc_f(m));
    }
}

// ---------------- CSR build ----------------
__global__ void k_zero_cnt() {
    int i = blockIdx.x * blockDim.x + threadIdx.x;
    if (i < N_NODES) g_cnt[i] = 0;
}

__global__ void k_hist(const int* __restrict__ ei) {
    int e = blockIdx.x * blockDim.x + threadIdx.x;
    if (e >= E_TOT) return;
    int d = (e < N_EDGES) ? ei[N_EDGES + e] : e - N_EDGES;   // int32 (JAX x64 disabled)
    atomicAdd(&g_cnt[d], 1);
}

__global__ void k_blocksum() {
    __shared__ int sm[SCAN_BS];
    int i = blockIdx.x * SCAN_BS + threadIdx.x;
    sm[threadIdx.x] = (i < N_NODES) ? g_cnt[i] : 0;
    __syncthreads();
    for (int o = SCAN_BS / 2; o > 0; o >>= 1) {
        if (threadIdx.x < o) sm[threadIdx.x] += sm[threadIdx.x + o];
        __syncthreads();
    }
    if (threadIdx.x == 0) {
        g_bsum[blockIdx.x] = sm[0];
        if (blockIdx.x == 0) { g_maxas[0] = 0u; g_maxas[1] = 0u; g_maxas[2] = 0u; }
    }
}

// offsets: intra-block Hillis-Steele scan + on-the-fly block prefix from raw g_bsum
__global__ void k_offsets() {
    __shared__ int sm[SCAN_BS];
    __shared__ int sb[128];
    int t = threadIdx.x;
    int i = blockIdx.x * SCAN_BS + t;
    int v = (i < N_NODES) ? g_cnt[i] : 0;
    sm[t] = v;
    if (t < 128) {
        int bv = (t < NBLK && t < blockIdx.x) ? g_bsum[t] : 0;
        sb[t] = bv;
    }
    __syncthreads();
    for (int o = 64; o > 0; o >>= 1) {
        if (t < o) sb[t] += sb[t + o];
        __syncthreads();
    }
    for (int o = 1; o < SCAN_BS; o <<= 1) {
        int u = (t >= o) ? sm[t - o] : 0;
        __syncthreads();
        sm[t] += u;
        __syncthreads();
    }
    if (i < N_NODES) {
        int excl = sm[t] - v + sb[0];
        g_off[i] = excl;
        g_cur[i] = excl;
        if (i == N_NODES - 1) g_off[N_NODES] = excl + v;   // == E_TOT
    }
}

__global__ void k_fill(const int* __restrict__ ei) {
    int e = blockIdx.x * blockDim.x + threadIdx.x;
    if (e >= E_TOT) return;
    int s, d;
    if (e < N_EDGES) { s = ei[e]; d = ei[N_EDGES + e]; }
    else             { s = d = e - N_EDGES; }
    int pos = atomicAdd(&g_cur[d], 1);
    g_ssrc[pos] = s;
}

// ---------------- helpers ----------------
__device__ __forceinline__ uint2 pack_half4(float a, float b, float c, float d) {
    __half2 h0 = __float22half2_rn(make_float2(a, b));
    __half2 h1 = __float22half2_rn(make_float2(c, d));
    uint2 u;
    u.x = *reinterpret_cast<unsigned*>(&h0);
    u.y = *reinterpret_cast<unsigned*>(&h1);
    return u;
}
__device__ __forceinline__ float4 unpack_half4(uint2 u) {
    __half2 h0 = *reinterpret_cast<__half2*>(&u.x);
    __half2 h1 = *reinterpret_cast<__half2*>(&u.y);
    float2 f0 = __half22float2(h0), f1 = __half22float2(h1);
    return make_float4(f0.x, f0.y, f1.x, f1.y);
}

// ---------------- layer 1 GEMM (K=13) + fused attention dots + block-reduced max --
__global__ void k_gemm1(const float* __restrict__ x, const float* __restrict__ W1,
                        const float* __restrict__ a_src, const float* __restrict__ a_dst) {
    __shared__ __align__(16) float Ws[IND * HID];
    __shared__ __align__(16) float As[HID];
    __shared__ __align__(16) float Ad[HID];
    __shared__ float smax[8];
    for (int i = threadIdx.x; i < IND * HID; i += blockDim.x) Ws[i] = W1[i];
    for (int i = threadIdx.x; i < HID; i += blockDim.x) { As[i] = a_src[i]; Ad[i] = a_dst[i]; }
    __syncthreads();
    int warp = threadIdx.x >> 5, lane = threadIdx.x & 31;
    int node = blockIdx.x * 8 + warp;     // grid is exact: 50000 = 6250*8, no partial block
    float xv[IND];
#pragma unroll
    for (int k = 0; k < IND; ++k) xv[k] = x[node * IND + k];
    float4 acc = {0.f, 0.f, 0.f, 0.f};
#pragma unroll
    for (int k = 0; k < IND; ++k) {
        float4 w = *(const float4*)&Ws[k * HID + lane * 4];
        acc.x += xv[k] * w.x; acc.y += xv[k] * w.y;
        acc.z += xv[k] * w.z; acc.w += xv[k] * w.w;
    }
    ((uint2*)g_hh)[node * 32 + lane] = pack_half4(acc.x, acc.y, acc.z, acc.w);
    float4 a1 = *(const float4*)&As[lane * 4];
    float4 a2 = *(const float4*)&Ad[lane * 4];
    float s1 = acc.x * a1.x + acc.y * a1.y + acc.z * a1.z + acc.w * a1.w;
    float s2 = acc.x * a2.x + acc.y * a2.y + acc.z * a2.z + acc.w * a2.w;
#pragma unroll
    for (int o = 16; o; o >>= 1) {
        s1 += __shfl_xor_sync(0xffffffffu, s1, o);
        s2 += __shfl_xor_sync(0xffffffffu, s2, o);
    }
    if (lane == 0) { g_as[node] = s1; g_ad[node] = s2; }
    block_atomic_max(&g_maxas[0], s1, warp, lane, smax);
}

// ---------------- W2 -> fp16 ----------------
__global__ void k_cvtW2(const float* __restrict__ W) {
    int i = blockIdx.x * blockDim.x + threadIdx.x;
    if (i < HID * HID) g_W2h[i] = __float2half(W[i]);
}

// ---------------- layer 2 GEMM via WMMA: 64 rows x 128 cols per block ----------
#define FS_LD 136
__global__ void k_gemm2_wmma() {
    __shared__ __align__(16) __half Fs[64 * FS_LD];
    __shared__ __align__(16) float  Os[8 * 256];       // per-warp 16x16 staging
    int rowBase = blockIdx.x * 64;
    int warp = threadIdx.x >> 5, lane = threadIdx.x & 31;
    for (int v = threadIdx.x * 8; v < 64 * HID; v += 256 * 8) {
        int r = v >> 7, c = v & 127;
        int gr = rowBase + r;
        uint4 d = (gr < N_NODES) ? *(const uint4*)&g_feath[gr * HID + c]
                                 : make_uint4(0u, 0u, 0u, 0u);
        *(uint4*)&Fs[r * FS_LD + c] = d;
    }
    __syncthreads();
    int rowTile = warp >> 1;
    int colTile0 = (warp & 1) * 4;
    wmma::fragment<wmma::accumulator, 16, 16, 16, float> acc[4];
#pragma unroll
    for (int t = 0; t < 4; ++t) wmma::fill_fragment(acc[t], 0.f);
    for (int k = 0; k < HID; k += 16) {
        wmma::fragment<wmma::matrix_a, 16, 16, 16, __half, wmma::row_major> a;
        wmma::load_matrix_sync(a, &Fs[rowTile * 16 * FS_LD + k], FS_LD);
#pragma unroll
        for (int t = 0; t < 4; ++t) {
            wmma::fragment<wmma::matrix_b, 16, 16, 16, __half, wmma::row_major> b;
            wmma::load_matrix_sync(b, &g_W2h[k * HID + (colTile0 + t) * 16], HID);
            wmma::mma_sync(acc[t], a, b, acc[t]);
        }
    }
    float* os = &Os[warp * 256];
#pragma unroll
    for (int t = 0; t < 4; ++t) {
        wmma::store_matrix_sync(os, acc[t], 16, wmma::mem_row_major);
        __syncwarp();
        int r = lane >> 1, c8 = (lane & 1) * 8;
        int gr = rowBase + rowTile * 16 + r;
        if (gr < N_NODES) {
            int gc = (colTile0 + t) * 16 + c8;
            const float* p = &os[r * 16 + c8];
            __half2* dst = (__half2*)&g_hh[gr * HID + gc];
#pragma unroll
            for (int q = 0; q < 4; ++q)
                dst[q] = __float22half2_rn(make_float2(p[2 * q], p[2 * q + 1]));
        }
        __syncwarp();
    }
}

// attention dots for layer 2 (h row . a_src / a_dst), h fp16; block-reduced max
__global__ void k_rowdot(const float* __restrict__ a_src, const float* __restrict__ a_dst) {
    __shared__ float smax[8];
    int warp = threadIdx.x >> 5, lane = threadIdx.x & 31;
    int node = blockIdx.x * 8 + warp;     // exact grid
    float4 hv = unpack_half4(((const uint2*)g_hh)[node * 32 + lane]);
    float4 a1 = make_float4(a_src[lane * 4], a_src[lane * 4 + 1], a_src[lane * 4 + 2], a_src[lane * 4 + 3]);
    float4 a2 = make_float4(a_dst[lane * 4], a_dst[lane * 4 + 1], a_dst[lane * 4 + 2], a_dst[lane * 4 + 3]);
    float s1 = hv.x * a1.x + hv.y * a1.y + hv.z * a1.z + hv.w * a1.w;
    float s2 = hv.x * a2.x + hv.y * a2.y + hv.z * a2.z + hv.w * a2.w;
#pragma unroll
    for (int o = 16; o; o >>= 1) {
        s1 += __shfl_xor_sync(0xffffffffu, s1, o);
        s2 += __shfl_xor_sync(0xffffffffu, s2, o);
    }
    if (lane == 0) { g_as[node] = s1; g_ad[node] = s2; }
    block_atomic_max(&g_maxas[1], s1, warp, lane, smax);
}

// ---------------- fused softmax-aggregation, F=128 (warp per node, fp16 gather) ----
// single edge pass: shift = leaky(global_max(as) + ad_i) >= all e_ij (softmax invariant)
__global__ void k_agg128(const float* __restrict__ b, int layer) {
    int warp = threadIdx.x >> 5, lane = threadIdx.x & 31;
    int i = blockIdx.x * 8 + warp;
    if (i >= N_NODES) return;
    int start = g_off[i], end = g_off[i + 1];
    float adi = g_ad[i];
    float m = leaky(dec_f(g_maxas[layer]) + adi);
    float4 acc = {0.f, 0.f, 0.f, 0.f};
    float denom = 0.f;
    const uint2* hh = (const uint2*)g_hh;
    int j = start;
    for (; j + 4 <= end; j += 4) {
        int s0 = g_ssrc[j], s1 = g_ssrc[j + 1], s2 = g_ssrc[j + 2], s3 = g_ssrc[j + 3];
        float e0 = g_as[s0] + adi, e1 = g_as[s1] + adi,
              e2 = g_as[s2] + adi, e3 = g_as[s3] + adi;
        uint2 p0 = hh[s0 * 32 + lane], p1 = hh[s1 * 32 + lane],
              p2 = hh[s2 * 32 + lane], p3 = hh[s3 * 32 + lane];
        float x0 = __expf(leaky(e0) - m), x1 = __expf(leaky(e1) - m),
              x2 = __expf(leaky(e2) - m), x3 = __expf(leaky(e3) - m);
        denom += (x0 + x1) + (x2 + x3);
        float4 h0 = unpack_half4(p0), h1 = unpack_half4(p1),
               h2 = unpack_half4(p2), h3 = unpack_half4(p3);
        acc.x += x0 * h0.x + x1 * h1.x + x2 * h2.x + x3 * h3.x;
        acc.y += x0 * h0.y + x1 * h1.y + x2 * h2.y + x3 * h3.y;
        acc.z += x0 * h0.z + x1 * h1.z + x2 * h2.z + x3 * h3.z;
        acc.w += x0 * h0.w + x1 * h1.w + x2 * h2.w + x3 * h3.w;
    }
    for (; j < end; ++j) {
        int s = g_ssrc[j];
        float ex = __expf(leaky(g_as[s] + adi) - m);
        denom += ex;
        float4 hv = unpack_half4(hh[s * 32 + lane]);
        acc.x += ex * hv.x; acc.y += ex * hv.y;
        acc.z += ex * hv.z; acc.w += ex * hv.w;
    }
    float inv = 1.f / (denom + 1e-16f);
    float4 bv = make_float4(b[lane * 4], b[lane * 4 + 1], b[lane * 4 + 2], b[lane * 4 + 3]);
    float4 r;
    r.x = fmaxf(acc.x * inv + bv.x, 0.f); r.y = fmaxf(acc.y * inv + bv.y, 0.f);
    r.z = fmaxf(acc.z * inv + bv.z, 0.f); r.w = fmaxf(acc.w * inv + bv.w, 0.f);
    ((uint2*)g_feath)[i * 32 + lane] = pack_half4(r.x, r.y, r.z, r.w);
}

// ---------------- layer 3 GEMM (K=128 -> 5, fp16 input) + dots + block max --------
__global__ void k_gemm3(const float* __restrict__ W3,
                        const float* __restrict__ a_src, const float* __restrict__ a_dst) {
    __shared__ float Ws[HID * OUTD];
    __shared__ float As[OUTD], Ad[OUTD];
    __shared__ float smax[8];
    for (int i = threadIdx.x; i < HID * OUTD; i += blockDim.x) Ws[i] = W3[i];
    if (threadIdx.x < OUTD) { As[threadIdx.x] = a_src[threadIdx.x]; Ad[threadIdx.x] = a_dst[threadIdx.x]; }
    __syncthreads();
    int warp = threadIdx.x >> 5, lane = threadIdx.x & 31;
    int node = blockIdx.x * 8 + warp;     // exact grid
    float4 f = unpack_half4(((const uint2*)g_feath)[node * 32 + lane]);
    int k0 = lane * 4;
    float hc[OUTD];
#pragma unroll
    for (int c = 0; c < OUTD; ++c) {
        float s = f.x * Ws[(k0 + 0) * OUTD + c] + f.y * Ws[(k0 + 1) * OUTD + c]
                + f.z * Ws[(k0 + 2) * OUTD + c] + f.w * Ws[(k0 + 3) * OUTD + c];
#pragma unroll
        for (int o = 16; o; o >>= 1) s += __shfl_xor_sync(0xffffffffu, s, o);
        hc[c] = s;
    }
    float s1 = 0.f;
    if (lane == 0) {
        float s2 = 0.f;
#pragma unroll
        for (int c = 0; c < OUTD; ++c) {
            g_h5[node * OUTD + c] = hc[c];
            s1 += hc[c] * As[c];
            s2 += hc[c] * Ad[c];
        }
        g_as[node] = s1; g_ad[node] = s2;
    }
    block_atomic_max(&g_maxas[2], s1, warp, lane, smax);
}

// ---------------- fused aggregation F=5 + bias + log_softmax (warp per node) -------
__global__ void k_agg5(const float* __restrict__ b3, float* __restrict__ out) {
    int warp = threadIdx.x >> 5, lane = threadIdx.x & 31;
    int i = blockIdx.x * 8 + warp;
    if (i >= N_NODES) return;
    int start = g_off[i], end = g_off[i + 1];
    float adi = g_ad[i];
    float m = leaky(dec_f(g_maxas[2]) + adi);
    float a0 = 0.f, a1 = 0.f, a2 = 0.f, a3 = 0.f, a4 = 0.f, denom = 0.f;
    for (int j = start + lane; j < end; j += 32) {
        int s = g_ssrc[j];
        float ex = __expf(leaky(g_as[s] + adi) - m);
        denom += ex;
        const float* hp = &g_h5[s * OUTD];
        a0 += ex * hp[0]; a1 += ex * hp[1]; a2 += ex * hp[2];
        a3 += ex * hp[3]; a4 += ex * hp[4];
    }
#pragma unroll
    for (int o = 16; o; o >>= 1) {
        denom += __shfl_xor_sync(0xffffffffu, denom, o);
        a0 += __shfl_xor_sync(0xffffffffu, a0, o);
        a1 += __shfl_xor_sync(0xffffffffu, a1, o);
        a2 += __shfl_xor_sync(0xffffffffu, a2, o);
        a3 += __shfl_xor_sync(0xffffffffu, a3, o);
        a4 += __shfl_xor_sync(0xffffffffu, a4, o);
    }
    if (lane == 0) {
        float inv = 1.f / (denom + 1e-16f);
        float v[OUTD] = {a0 * inv + b3[0], a1 * inv + b3[1], a2 * inv + b3[2],
                         a3 * inv + b3[3], a4 * inv + b3[4]};
        float mx = -1e30f;
#pragma unroll
        for (int c = 0; c < OUTD; ++c) mx = fmaxf(mx, v[c]);
        float se = 0.f;
#pragma unroll
        for (int c = 0; c < OUTD; ++c) se += __expf(v[c] - mx);
        float lse = mx + logf(se);
#pragma unroll
        for (int c = 0; c < OUTD; ++c) out[i * OUTD + c] = v[c] - lse;
    }
}

// ---------------- launch ----------------
extern "C" void kernel_launch(void* const* d_in, const int* in_sizes, int n_in,
                              void* d_out, int out_size) {
    const float* x   = (const float*)d_in[0];
    const int*   ei  = (const int*)d_in[1];       // int32: JAX x64 is disabled
    const float* W1  = (const float*)d_in[2];
    const float* as1 = (const float*)d_in[3];
    const float* ad1 = (const float*)d_in[4];
    const float* b1  = (const float*)d_in[5];
    const float* W2  = (const float*)d_in[6];
    const float* as2 = (const float*)d_in[7];
    const float* ad2 = (const float*)d_in[8];
    const float* b2  = (const float*)d_in[9];
    const float* W3  = (const float*)d_in[10];
    const float* as3 = (const float*)d_in[11];
    const float* ad3 = (const float*)d_in[12];
    const float* b3  = (const float*)d_in[13];
    float* out = (float*)d_out;

    // CSR build (shared by all 3 layers; rebuilt every call — no caching)
    k_zero_cnt<<<(N_NODES + 255) / 256, 256>>>();
    k_hist<<<(E_TOT + 255) / 256, 256>>>(ei);
    k_blocksum<<<NBLK, SCAN_BS>>>();
    k_offsets<<<NBLK, SCAN_BS>>>();
    k_fill<<<(E_TOT + 255) / 256, 256>>>(ei);

    int nwb = N_NODES / 8;   // 6250, exact — warp-per-node grids

    // layer 1 (+ W2 conversion, independent)
    k_cvtW2<<<(HID * HID + 255) / 256, 256>>>(W2);
    k_gemm1<<<nwb, 256>>>(x, W1, as1, ad1);
    k_agg128<<<nwb, 256>>>(b1, 0);
    // layer 2
    k_gemm2_wmma<<<(N_NODES + 63) / 64, 256>>>();
    k_rowdot<<<nwb, 256>>>(as2, ad2);
    k_agg128<<<nwb, 256>>>(b2, 1);
    // layer 3
    k_gemm3<<<nwb, 256>>>(W3, as3, ad3);
    k_agg5<<<nwb, 256>>>(b3, out);
}

// round 13
// speedup vs baseline: 1.2574x; 1.0306x over previous
#include <cuda_runtime.h>
#include <cuda_fp16.h>
#include <mma.h>
#include <math.h>

using namespace nvcuda;

#define N_NODES 50000
#define N_EDGES 1600000
#define E_TOT   (N_EDGES + N_NODES)
#define HID     128
#define IND     13
#define OUTD    5
#define SCAN_BS 512
#define NBLK    ((N_NODES + SCAN_BS - 1) / SCAN_BS)   // 98

// ---------------- scratch (static device globals; no allocation) ----------------
__device__ int      g_ssrc[E_TOT];           // CSR-sorted source indices (by dst)
__device__ int      g_cnt[N_NODES];
__device__ int      g_off[N_NODES + 1];
__device__ int      g_cur[N_NODES];
__device__ unsigned g_maxas[3];              // per-layer global max of a_src·h (encoded)
__device__ __align__(16) __half g_hh[N_NODES * HID];    // transformed features, fp16
__device__ __align__(16) __half g_feath[N_NODES * HID]; // layer input, fp16
__device__ __align__(16) __half g_W2h[HID * HID];       // W2 in fp16
__device__ float    g_as[N_NODES];
__device__ float    g_ad[N_NODES];
__device__ float    g_h5[N_NODES * OUTD];

// order-preserving float<->uint encoding (atomicMax-able, order-invariant => deterministic)
__device__ __forceinline__ unsigned enc_f(float f) {
    unsigned u = __float_as_uint(f);
    return (u >> 31) ? ~u : (u | 0x80000000u);
}
__device__ __forceinline__ float dec_f(unsigned e) {
    return __uint_as_float((e >> 31) ? (e ^ 0x80000000u) : ~e);
}
__device__ __forceinline__ float leaky(float e) { return e > 0.f ? e : 0.2f * e; }

// block-level (8 warps) max reduce then ONE atomic per block
__device__ __forceinline__ void block_atomic_max(unsigned* dst, float s1, int warp, int lane,
                                                 float* smax) {
    if (lane == 0) smax[warp] = s1;
    __syncthreads();
    if (threadIdx.x == 0) {
        float m = smax[0];
#pragma unroll
        for (int w = 1; w < 8; ++w) m = fmaxf(m, smax[w]);
        atomicMax(dst, enc_f(m));
    }
}

// ---------------- init: cnt=1 (self loops pre-counted) + W2->fp16 + maxas ----------
__global__ void k_init(const float* __restrict__ W2) {
    int i = blockIdx.x * blockDim.x + threadIdx.x;
    if (i < N_NODES) g_cnt[i] = 1;                 // self-loop contribution
    if (i < HID * HID) g_W2h[i] = __float2half(W2[i]);
    if (i < 3) g_maxas[i] = 0u;
}

// ---------------- CSR build ----------------
__global__ void k_hist(const int* __restrict__ ei) {   // real edges only, int4
    int e4 = blockIdx.x * blockDim.x + threadIdx.x;
    if (e4 >= N_EDGES / 4) return;
    int4 d = ((const int4*)(ei + N_EDGES))[e4];        // dst half (int32: JAX x64 disabled)
    atomicAdd(&g_cnt[d.x], 1);
    atomicAdd(&g_cnt[d.y], 1);
    atomicAdd(&g_cnt[d.z], 1);
    atomicAdd(&g_cnt[d.w], 1);
}

// offsets: block prefix computed in-kernel (strided sum over preceding counts) + scan
__global__ void k_offsets() {
    __shared__ int sm[SCAN_BS];
    int t = threadIdx.x;
    int base = blockIdx.x * SCAN_BS;
    int pre = 0;
    for (int i = t; i < base; i += SCAN_BS) pre += g_cnt[i];
    sm[t] = pre;
    __syncthreads();
    for (int o = SCAN_BS / 2; o > 0; o >>= 1) {
        if (t < o) sm[t] += sm[t + o];
        __syncthreads();
    }
    int blockpre = sm[0];
    __syncthreads();
    int i = base + t;
    int v = (i < N_NODES) ? g_cnt[i] : 0;
    sm[t] = v;
    __syncthreads();
    for (int o = 1; o < SCAN_BS; o <<= 1) {
        int u = (t >= o) ? sm[t - o] : 0;
        __syncthreads();
        sm[t] += u;
        __syncthreads();
    }
    if (i < N_NODES) {
        int excl = sm[t] - v + blockpre;
        g_off[i] = excl;
        g_cur[i] = excl;
        if (i == N_NODES - 1) g_off[N_NODES] = excl + v;   // == E_TOT
    }
}

__global__ void k_fill(const int* __restrict__ ei) {   // int4 edges + self-loop tail
    int e4 = blockIdx.x * blockDim.x + threadIdx.x;
    const int nE4 = N_EDGES / 4;
    if (e4 < nE4) {
        int4 s = ((const int4*)ei)[e4];
        int4 d = ((const int4*)(ei + N_EDGES))[e4];
        g_ssrc[atomicAdd(&g_cur[d.x], 1)] = s.x;
        g_ssrc[atomicAdd(&g_cur[d.y], 1)] = s.y;
        g_ssrc[atomicAdd(&g_cur[d.z], 1)] = s.z;
        g_ssrc[atomicAdd(&g_cur[d.w], 1)] = s.w;
    } else {
        int n0 = (e4 - nE4) * 4;
#pragma unroll
        for (int k = 0; k < 4; ++k) {
            int n = n0 + k;
            if (n < N_NODES) g_ssrc[atomicAdd(&g_cur[n], 1)] = n;
        }
    }
}

// ---------------- helpers ----------------
__device__ __forceinline__ uint2 pack_half4(float a, float b, float c, float d) {
    __half2 h0 = __float22half2_rn(make_float2(a, b));
    __half2 h1 = __float22half2_rn(make_float2(c, d));
    uint2 u;
    u.x = *reinterpret_cast<unsigned*>(&h0);
    u.y = *reinterpret_cast<unsigned*>(&h1);
    return u;
}
__device__ __forceinline__ float4 unpack_half4(uint2 u) {
    __half2 h0 = *reinterpret_cast<__half2*>(&u.x);
    __half2 h1 = *reinterpret_cast<__half2*>(&u.y);
    float2 f0 = __half22float2(h0), f1 = __half22float2(h1);
    return make_float4(f0.x, f0.y, f1.x, f1.y);
}

// ---------------- layer 1 GEMM (K=13) + fused attention dots + block-reduced max --
__global__ void k_gemm1(const float* __restrict__ x, const float* __restrict__ W1,
                        const float* __restrict__ a_src, const float* __restrict__ a_dst) {
    __shared__ __align__(16) float Ws[IND * HID];
    __shared__ __align__(16) float As[HID];
    __shared__ __align__(16) float Ad[HID];
    __shared__ float smax[8];
    for (int i = threadIdx.x; i < IND * HID; i += blockDim.x) Ws[i] = W1[i];
    for (int i = threadIdx.x; i < HID; i += blockDim.x) { As[i] = a_src[i]; Ad[i] = a_dst[i]; }
    __syncthreads();
    int warp = threadIdx.x >> 5, lane = threadIdx.x & 31;
    int node = blockIdx.x * 8 + warp;     // exact: 50000 = 6250*8
    float xv[IND];
#pragma unroll
    for (int k = 0; k < IND; ++k) xv[k] = x[node * IND + k];
    float4 acc = {0.f, 0.f, 0.f, 0.f};
#pragma unroll
    for (int k = 0; k < IND; ++k) {
        float4 w = *(const float4*)&Ws[k * HID + lane * 4];
        acc.x += xv[k] * w.x; acc.y += xv[k] * w.y;
        acc.z += xv[k] * w.z; acc.w += xv[k] * w.w;
    }
    ((uint2*)g_hh)[node * 32 + lane] = pack_half4(acc.x, acc.y, acc.z, acc.w);
    float4 a1 = *(const float4*)&As[lane * 4];
    float4 a2 = *(const float4*)&Ad[lane * 4];
    float s1 = acc.x * a1.x + acc.y * a1.y + acc.z * a1.z + acc.w * a1.w;
    float s2 = acc.x * a2.x + acc.y * a2.y + acc.z * a2.z + acc.w * a2.w;
#pragma unroll
    for (int o = 16; o; o >>= 1) {
        s1 += __shfl_xor_sync(0xffffffffu, s1, o);
        s2 += __shfl_xor_sync(0xffffffffu, s2, o);
    }
    if (lane == 0) { g_as[node] = s1; g_ad[node] = s2; }
    block_atomic_max(&g_maxas[0], s1, warp, lane, smax);
}

// ---------------- layer 2 GEMM via WMMA + fused attention dots -------------------
// block 256 (8 warps), 64 rows x 128 cols. Warp w: row-tile w>>1, col-tiles (w&1)*4..+3.
#define FS_LD 136
__global__ void k_gemm2_wmma(const float* __restrict__ a_src, const float* __restrict__ a_dst) {
    __shared__ __align__(16) __half Fs[64 * FS_LD];
    __shared__ __align__(16) float  Os[8 * 256];       // per-warp 16x16 staging
    __shared__ float Asm[HID], Adm[HID];
    __shared__ float s_as[64], s_ad[64];
    int rowBase = blockIdx.x * 64;
    int warp = threadIdx.x >> 5, lane = threadIdx.x & 31;
    if (threadIdx.x < HID) { Asm[threadIdx.x] = a_src[threadIdx.x]; Adm[threadIdx.x] = a_dst[threadIdx.x]; }
    if (threadIdx.x < 64) { s_as[threadIdx.x] = 0.f; s_ad[threadIdx.x] = 0.f; }
    for (int v = threadIdx.x * 8; v < 64 * HID; v += 256 * 8) {
        int r = v >> 7, c = v & 127;
        int gr = rowBase + r;
        uint4 d = (gr < N_NODES) ? *(const uint4*)&g_feath[gr * HID + c]
                                 : make_uint4(0u, 0u, 0u, 0u);
        *(uint4*)&Fs[r * FS_LD + c] = d;
    }
    __syncthreads();
    int rowTile = warp >> 1;
    int colTile0 = (warp & 1) * 4;
    wmma::fragment<wmma::accumulator, 16, 16, 16, float> acc[4];
#pragma unroll
    for (int t = 0; t < 4; ++t) wmma::fill_fragment(acc[t], 0.f);
    for (int k = 0; k < HID; k += 16) {
        wmma::fragment<wmma::matrix_a, 16, 16, 16, __half, wmma::row_major> a;
        wmma::load_matrix_sync(a, &Fs[rowTile * 16 * FS_LD + k], FS_LD);
#pragma unroll
        for (int t = 0; t < 4; ++t) {
            wmma::fragment<wmma::matrix_b, 16, 16, 16, __half, wmma::row_major> b;
            wmma::load_matrix_sync(b, &g_W2h[k * HID + (colTile0 + t) * 16], HID);
            wmma::mma_sync(acc[t], a, b, acc[t]);
        }
    }
    float* os = &Os[warp * 256];
#pragma unroll
    for (int t = 0; t < 4; ++t) {
        wmma::store_matrix_sync(os, acc[t], 16, wmma::mem_row_major);
        __syncwarp();
        int r = lane >> 1, c8 = (lane & 1) * 8;
        int gr = rowBase + rowTile * 16 + r;
        int gc = (colTile0 + t) * 16 + c8;
        const float* p = &os[r * 16 + c8];
        if (gr < N_NODES) {
            __half2* dst = (__half2*)&g_hh[gr * HID + gc];
#pragma unroll
            for (int q = 0; q < 4; ++q)
                dst[q] = __float22half2_rn(make_float2(p[2 * q], p[2 * q + 1]));
        }
        // fused attention-dot partials (8 cols each)
        float ps = 0.f, pd = 0.f;
#pragma unroll
        for (int q = 0; q < 8; ++q) { ps += p[q] * Asm[gc + q]; pd += p[q] * Adm[gc + q]; }
        atomicAdd(&s_as[rowTile * 16 + r], ps);
        atomicAdd(&s_ad[rowTile * 16 + r], pd);
        __syncwarp();
    }
    __syncthreads();
    if (warp == 0) {
        float m = -1e30f;
#pragma unroll
        for (int it = 0; it < 2; ++it) {
            int rr = it * 32 + lane;
            int gr = rowBase + rr;
            if (gr < N_NODES) {
                float s1 = s_as[rr];
                g_as[gr] = s1;
                g_ad[gr] = s_ad[rr];
                m = fmaxf(m, s1);
            }
        }
#pragma unroll
        for (int o = 16; o; o >>= 1) m = fmaxf(m, __shfl_xor_sync(0xffffffffu, m, o));
        if (lane == 0) atomicMax(&g_maxas[1], enc_f(m));
    }
}

// ---------------- fused softmax-aggregation, F=128 (warp per node, fp16 gather) ----
// single edge pass: shift = leaky(global_max(as) + ad_i) >= all e_ij (softmax invariant)
__global__ void k_agg128(const float* __restrict__ b, int layer) {
    int warp = threadIdx.x >> 5, lane = threadIdx.x & 31;
    int i = blockIdx.x * 8 + warp;
    if (i >= N_NODES) return;
    int start = g_off[i], end = g_off[i + 1];
    float adi = g_ad[i];
    float m = leaky(dec_f(g_maxas[layer]) + adi);
    float4 acc = {0.f, 0.f, 0.f, 0.f};
    float denom = 0.f;
    const uint2* hh = (const uint2*)g_hh;
    int j = start;
    for (; j + 4 <= end; j += 4) {
        int s0 = g_ssrc[j], s1 = g_ssrc[j + 1], s2 = g_ssrc[j + 2], s3 = g_ssrc[j + 3];
        float e0 = g_as[s0] + adi, e1 = g_as[s1] + adi,
              e2 = g_as[s2] + adi, e3 = g_as[s3] + adi;
        uint2 p0 = hh[s0 * 32 + lane], p1 = hh[s1 * 32 + lane],
              p2 = hh[s2 * 32 + lane], p3 = hh[s3 * 32 + lane];
        float x0 = __expf(leaky(e0) - m), x1 = __expf(leaky(e1) - m),
              x2 = __expf(leaky(e2) - m), x3 = __expf(leaky(e3) - m);
        denom += (x0 + x1) + (x2 + x3);
        float4 h0 = unpack_half4(p0), h1 = unpack_half4(p1),
               h2 = unpack_half4(p2), h3 = unpack_half4(p3);
        acc.x += x0 * h0.x + x1 * h1.x + x2 * h2.x + x3 * h3.x;
        acc.y += x0 * h0.y + x1 * h1.y + x2 * h2.y + x3 * h3.y;
        acc.z += x0 * h0.z + x1 * h1.z + x2 * h2.z + x3 * h3.z;
        acc.w += x0 * h0.w + x1 * h1.w + x2 * h2.w + x3 * h3.w;
    }
    for (; j < end; ++j) {
        int s = g_ssrc[j];
        float ex = __expf(leaky(g_as[s] + adi) - m);
        denom += ex;
        float4 hv = unpack_half4(hh[s * 32 + lane]);
        acc.x += ex * hv.x; acc.y += ex * hv.y;
        acc.z += ex * hv.z; acc.w += ex * hv.w;
    }
    float inv = 1.f / (denom + 1e-16f);
    float4 bv = make_float4(b[lane * 4], b[lane * 4 + 1], b[lane * 4 + 2], b[lane * 4 + 3]);
    float4 r;
    r.x = fmaxf(acc.x * inv + bv.x, 0.f); r.y = fmaxf(acc.y * inv + bv.y, 0.f);
    r.z = fmaxf(acc.z * inv + bv.z, 0.f); r.w = fmaxf(acc.w * inv + bv.w, 0.f);
    ((uint2*)g_feath)[i * 32 + lane] = pack_half4(r.x, r.y, r.z, r.w);
}

// ---------------- layer 3 GEMM (K=128 -> 5, fp16 input) + dots + block max --------
__global__ void k_gemm3(const float* __restrict__ W3,
                        const float* __restrict__ a_src, const float* __restrict__ a_dst) {
    __shared__ float Ws[HID * OUTD];
    __shared__ float As[OUTD], Ad[OUTD];
    __shared__ float smax[8];
    for (int i = threadIdx.x; i < HID * OUTD; i += blockDim.x) Ws[i] = W3[i];
    if (threadIdx.x < OUTD) { As[threadIdx.x] = a_src[threadIdx.x]; Ad[threadIdx.x] = a_dst[threadIdx.x]; }
    __syncthreads();
    int warp = threadIdx.x >> 5, lane = threadIdx.x & 31;
    int node = blockIdx.x * 8 + warp;     // exact grid
    float4 f = unpack_half4(((const uint2*)g_feath)[node * 32 + lane]);
    int k0 = lane * 4;
    float hc[OUTD];
#pragma unroll
    for (int c = 0; c < OUTD; ++c) {
        float s = f.x * Ws[(k0 + 0) * OUTD + c] + f.y * Ws[(k0 + 1) * OUTD + c]
                + f.z * Ws[(k0 + 2) * OUTD + c] + f.w * Ws[(k0 + 3) * OUTD + c];
#pragma unroll
        for (int o = 16; o; o >>= 1) s += __shfl_xor_sync(0xffffffffu, s, o);
        hc[c] = s;
    }
    float s1 = 0.f;
    if (lane == 0) {
        float s2 = 0.f;
#pragma unroll
        for (int c = 0; c < OUTD; ++c) {
            g_h5[node * OUTD + c] = hc[c];
            s1 += hc[c] * As[c];
            s2 += hc[c] * Ad[c];
        }
        g_as[node] = s1; g_ad[node] = s2;
    }
    block_atomic_max(&g_maxas[2], s1, warp, lane, smax);
}

// ---------------- fused aggregation F=5 + bias + log_softmax (warp per node) -------
__global__ void k_agg5(const float* __restrict__ b3, float* __restrict__ out) {
    int warp = threadIdx.x >> 5, lane = threadIdx.x & 31;
    int i = blockIdx.x * 8 + warp;
    if (i >= N_NODES) return;
    int start = g_off[i], end = g_off[i + 1];
    float adi = g_ad[i];
    float m = leaky(dec_f(g_maxas[2]) + adi);
    float a0 = 0.f, a1 = 0.f, a2 = 0.f, a3 = 0.f, a4 = 0.f, denom = 0.f;
    for (int j = start + lane; j < end; j += 32) {
        int s = g_ssrc[j];
        float ex = __expf(leaky(g_as[s] + adi) - m);
        denom += ex;
        const float* hp = &g_h5[s * OUTD];
        a0 += ex * hp[0]; a1 += ex * hp[1]; a2 += ex * hp[2];
        a3 += ex * hp[3]; a4 += ex * hp[4];
    }
#pragma unroll
    for (int o = 16; o; o >>= 1) {
        denom += __shfl_xor_sync(0xffffffffu, denom, o);
        a0 += __shfl_xor_sync(0xffffffffu, a0, o);
        a1 += __shfl_xor_sync(0xffffffffu, a1, o);
        a2 += __shfl_xor_sync(0xffffffffu, a2, o);
        a3 += __shfl_xor_sync(0xffffffffu, a3, o);
        a4 += __shfl_xor_sync(0xffffffffu, a4, o);
    }
    if (lane == 0) {
        float inv = 1.f / (denom + 1e-16f);
        float v[OUTD] = {a0 * inv + b3[0], a1 * inv + b3[1], a2 * inv + b3[2],
                         a3 * inv + b3[3], a4 * inv + b3[4]};
        float mx = -1e30f;
#pragma unroll
        for (int c = 0; c < OUTD; ++c) mx = fmaxf(mx, v[c]);
        float se = 0.f;
#pragma unroll
        for (int c = 0; c < OUTD; ++c) se += __expf(v[c] - mx);
        float lse = mx + logf(se);
#pragma unroll
        for (int c = 0; c < OUTD; ++c) out[i * OUTD + c] = v[c] - lse;
    }
}

// ---------------- launch ----------------
extern "C" void kernel_launch(void* const* d_in, const int* in_sizes, int n_in,
                              void* d_out, int out_size) {
    const float* x   = (const float*)d_in[0];
    const int*   ei  = (const int*)d_in[1];       // int32: JAX x64 is disabled
    const float* W1  = (const float*)d_in[2];
    const float* as1 = (const float*)d_in[3];
    const float* ad1 = (const float*)d_in[4];
    const float* b1  = (const float*)d_in[5];
    const float* W2  = (const float*)d_in[6];
    const float* as2 = (const float*)d_in[7];
    const float* ad2 = (const float*)d_in[8];
    const float* b2  = (const float*)d_in[9];
    const float* W3  = (const float*)d_in[10];
    const float* as3 = (const float*)d_in[11];
    const float* ad3 = (const float*)d_in[12];
    const float* b3  = (const float*)d_in[13];
    float* out = (float*)d_out;

    // CSR build (rebuilt every call — no caching)
    k_init<<<(N_NODES + 255) / 256, 256>>>(W2);
    k_hist<<<(N_EDGES / 4 + 255) / 256, 256>>>(ei);
    k_offsets<<<NBLK, SCAN_BS>>>();
    {
        int nthreads = N_EDGES / 4 + (N_NODES + 3) / 4;
        k_fill<<<(nthreads + 255) / 256, 256>>>(ei);
    }

    int nwb = N_NODES / 8;   // 6250, exact — warp-per-node grids

    // layer 1
    k_gemm1<<<nwb, 256>>>(x, W1, as1, ad1);
    k_agg128<<<nwb, 256>>>(b1, 0);
    // layer 2 (rowdot fused into GEMM epilogue)
    k_gemm2_wmma<<<(N_NODES + 63) / 64, 256>>>(as2, ad2);
    k_agg128<<<nwb, 256>>>(b2, 1);
    // layer 3
    k_gemm3<<<nwb, 256>>>(W3, as3, ad3);
    k_agg5<<<nwb, 256>>>(b3, out);
}

// round 14
// speedup vs baseline: 1.2676x; 1.0081x over previous
#include <cuda_runtime.h>
#include <cuda_fp16.h>
#include <mma.h>
#include <math.h>

using namespace nvcuda;

#define N_NODES 50000
#define N_EDGES 1600000
#define E_TOT   (N_EDGES + N_NODES)
#define HID     128
#define IND     13
#define OUTD    5
#define SCAN_BS 512
#define NBLK    ((N_NODES + SCAN_BS - 1) / SCAN_BS)   // 98

// ---------------- scratch (static device globals; no allocation) ----------------
__device__ int      g_ssrc[E_TOT];           // CSR-sorted source indices (by dst)
__device__ int      g_rank[N_EDGES];         // rank of edge within its dst bucket
__device__ int      g_cnt[N_NODES];
__device__ int      g_off[N_NODES + 1];
__device__ unsigned g_maxas[3];              // per-layer global max of a_src·h (encoded)
__device__ __align__(16) __half g_hh[N_NODES * HID];    // transformed features, fp16
__device__ __align__(16) __half g_feath[N_NODES * HID]; // layer input, fp16
__device__ __align__(16) __half g_W2h[HID * HID];       // W2 in fp16
__device__ float    g_as[N_NODES];
__device__ float    g_ad[N_NODES];
__device__ float    g_h5[N_NODES * OUTD];

// order-preserving float<->uint encoding (atomicMax-able, order-invariant => deterministic)
__device__ __forceinline__ unsigned enc_f(float f) {
    unsigned u = __float_as_uint(f);
    return (u >> 31) ? ~u : (u | 0x80000000u);
}
__device__ __forceinline__ float dec_f(unsigned e) {
    return __uint_as_float((e >> 31) ? (e ^ 0x80000000u) : ~e);
}
__device__ __forceinline__ float leaky(float e) { return e > 0.f ? e : 0.2f * e; }

// block-level (8 warps) max reduce then ONE atomic per block
__device__ __forceinline__ void block_atomic_max(unsigned* dst, float s1, int warp, int lane,
                                                 float* smax) {
    if (lane == 0) smax[warp] = s1;
    __syncthreads();
    if (threadIdx.x == 0) {
        float m = smax[0];
#pragma unroll
        for (int w = 1; w < 8; ++w) m = fmaxf(m, smax[w]);
        atomicMax(dst, enc_f(m));
    }
}

// ---------------- init: cnt=0 + W2->fp16 + maxas ----------
__global__ void k_init(const float* __restrict__ W2) {
    int i = blockIdx.x * blockDim.x + threadIdx.x;
    if (i < N_NODES) g_cnt[i] = 0;
    if (i < HID * HID) g_W2h[i] = __float2half(W2[i]);
    if (i < 3) g_maxas[i] = 0u;
}

// ---------------- CSR build ----------------
// hist: count real edges per dst AND record each edge's rank within its bucket
__global__ void k_hist(const int* __restrict__ ei) {
    int e4 = blockIdx.x * blockDim.x + threadIdx.x;
    if (e4 >= N_EDGES / 4) return;
    int4 d = ((const int4*)(ei + N_EDGES))[e4];        // dst half (int32: JAX x64 disabled)
    int4 r;
    r.x = atomicAdd(&g_cnt[d.x], 1);
    r.y = atomicAdd(&g_cnt[d.y], 1);
    r.z = atomicAdd(&g_cnt[d.z], 1);
    r.w = atomicAdd(&g_cnt[d.w], 1);
    ((int4*)g_rank)[e4] = r;
}

// offsets: block prefix via strided sum (+1 per node for self-loop) + intra-block scan.
// Also places each node's self-loop at slot off[i] (bucket position 0).
__global__ void k_offsets() {
    __shared__ int sm[SCAN_BS];
    int t = threadIdx.x;
    int base = blockIdx.x * SCAN_BS;
    int pre = 0;
    for (int i = t; i < base; i += SCAN_BS) pre += g_cnt[i];
    sm[t] = pre;
    __syncthreads();
    for (int o = SCAN_BS / 2; o > 0; o >>= 1) {
        if (t < o) sm[t] += sm[t + o];
        __syncthreads();
    }
    int blockpre = sm[0] + base;            // +1 self-loop for each preceding node
    __syncthreads();
    int i = base + t;
    int v = (i < N_NODES) ? g_cnt[i] + 1 : 0;   // +1 = self-loop
    sm[t] = v;
    __syncthreads();
    for (int o = 1; o < SCAN_BS; o <<= 1) {
        int u = (t >= o) ? sm[t - o] : 0;
        __syncthreads();
        sm[t] += u;
        __syncthreads();
    }
    if (i < N_NODES) {
        int excl = sm[t] - v + blockpre;
        g_off[i] = excl;
        g_ssrc[excl] = i;                   // self-loop occupies bucket slot 0
        if (i == N_NODES - 1) g_off[N_NODES] = excl + v;   // == E_TOT
    }
}

// fill: atomic-free scatter — pos = off[dst] + 1 + rank
__global__ void k_fill(const int* __restrict__ ei) {
    int e4 = blockIdx.x * blockDim.x + threadIdx.x;
    if (e4 >= N_EDGES / 4) return;
    int4 s = ((const int4*)ei)[e4];
    int4 d = ((const int4*)(ei + N_EDGES))[e4];
    int4 r = ((const int4*)g_rank)[e4];
    g_ssrc[g_off[d.x] + 1 + r.x] = s.x;
    g_ssrc[g_off[d.y] + 1 + r.y] = s.y;
    g_ssrc[g_off[d.z] + 1 + r.z] = s.z;
    g_ssrc[g_off[d.w] + 1 + r.w] = s.w;
}

// ---------------- helpers ----------------
__device__ __forceinline__ uint2 pack_half4(float a, float b, float c, float d) {
    __half2 h0 = __float22half2_rn(make_float2(a, b));
    __half2 h1 = __float22half2_rn(make_float2(c, d));
    uint2 u;
    u.x = *reinterpret_cast<unsigned*>(&h0);
    u.y = *reinterpret_cast<unsigned*>(&h1);
    return u;
}
__device__ __forceinline__ float4 unpack_half4(uint2 u) {
    __half2 h0 = *reinterpret_cast<__half2*>(&u.x);
    __half2 h1 = *reinterpret_cast<__half2*>(&u.y);
    float2 f0 = __half22float2(h0), f1 = __half22float2(h1);
    return make_float4(f0.x, f0.y, f1.x, f1.y);
}

// ---------------- layer 1 GEMM (K=13) + fused attention dots + block-reduced max --
__global__ void k_gemm1(const float* __restrict__ x, const float* __restrict__ W1,
                        const float* __restrict__ a_src, const float* __restrict__ a_dst) {
    __shared__ __align__(16) float Ws[IND * HID];
    __shared__ __align__(16) float As[HID];
    __shared__ __align__(16) float Ad[HID];
    __shared__ float smax[8];
    for (int i = threadIdx.x; i < IND * HID; i += blockDim.x) Ws[i] = W1[i];
    for (int i = threadIdx.x; i < HID; i += blockDim.x) { As[i] = a_src[i]; Ad[i] = a_dst[i]; }
    __syncthreads();
    int warp = threadIdx.x >> 5, lane = threadIdx.x & 31;
    int node = blockIdx.x * 8 + warp;     // exact: 50000 = 6250*8
    float xv[IND];
#pragma unroll
    for (int k = 0; k < IND; ++k) xv[k] = x[node * IND + k];
    float4 acc = {0.f, 0.f, 0.f, 0.f};
#pragma unroll
    for (int k = 0; k < IND; ++k) {
        float4 w = *(const float4*)&Ws[k * HID + lane * 4];
        acc.x += xv[k] * w.x; acc.y += xv[k] * w.y;
        acc.z += xv[k] * w.z; acc.w += xv[k] * w.w;
    }
    ((uint2*)g_hh)[node * 32 + lane] = pack_half4(acc.x, acc.y, acc.z, acc.w);
    float4 a1 = *(const float4*)&As[lane * 4];
    float4 a2 = *(const float4*)&Ad[lane * 4];
    float s1 = acc.x * a1.x + acc.y * a1.y + acc.z * a1.z + acc.w * a1.w;
    float s2 = acc.x * a2.x + acc.y * a2.y + acc.z * a2.z + acc.w * a2.w;
#pragma unroll
    for (int o = 16; o; o >>= 1) {
        s1 += __shfl_xor_sync(0xffffffffu, s1, o);
        s2 += __shfl_xor_sync(0xffffffffu, s2, o);
    }
    if (lane == 0) { g_as[node] = s1; g_ad[node] = s2; }
    block_atomic_max(&g_maxas[0], s1, warp, lane, smax);
}

// ---------------- layer 2 GEMM via WMMA + fused attention dots -------------------
// block 256 (8 warps), 64 rows x 128 cols. Warp w: row-tile w>>1, col-tiles (w&1)*4..+3.
#define FS_LD 136
__global__ void k_gemm2_wmma(const float* __restrict__ a_src, const float* __restrict__ a_dst) {
    __shared__ __align__(16) __half Fs[64 * FS_LD];
    __shared__ __align__(16) float  Os[8 * 256];       // per-warp 16x16 staging
    __shared__ float Asm[HID], Adm[HID];
    __shared__ float s_as[64], s_ad[64];
    int rowBase = blockIdx.x * 64;
    int warp = threadIdx.x >> 5, lane = threadIdx.x & 31;
    if (threadIdx.x < HID) { Asm[threadIdx.x] = a_src[threadIdx.x]; Adm[threadIdx.x] = a_dst[threadIdx.x]; }
    if (threadIdx.x < 64) { s_as[threadIdx.x] = 0.f; s_ad[threadIdx.x] = 0.f; }
    for (int v = threadIdx.x * 8; v < 64 * HID; v += 256 * 8) {
        int r = v >> 7, c = v & 127;
        int gr = rowBase + r;
        uint4 d = (gr < N_NODES) ? *(const uint4*)&g_feath[gr * HID + c]
                                 : make_uint4(0u, 0u, 0u, 0u);
        *(uint4*)&Fs[r * FS_LD + c] = d;
    }
    __syncthreads();
    int rowTile = warp >> 1;
    int colTile0 = (warp & 1) * 4;
    wmma::fragment<wmma::accumulator, 16, 16, 16, float> acc[4];
#pragma unroll
    for (int t = 0; t < 4; ++t) wmma::fill_fragment(acc[t], 0.f);
    for (int k = 0; k < HID; k += 16) {
        wmma::fragment<wmma::matrix_a, 16, 16, 16, __half, wmma::row_major> a;
        wmma::load_matrix_sync(a, &Fs[rowTile * 16 * FS_LD + k], FS_LD);
#pragma unroll
        for (int t = 0; t < 4; ++t) {
            wmma::fragment<wmma::matrix_b, 16, 16, 16, __half, wmma::row_major> b;
            wmma::load_matrix_sync(b, &g_W2h[k * HID + (colTile0 + t) * 16], HID);
            wmma::mma_sync(acc[t], a, b, acc[t]);
        }
    }
    float* os = &Os[warp * 256];
#pragma unroll
    for (int t = 0; t < 4; ++t) {
        wmma::store_matrix_sync(os, acc[t], 16, wmma::mem_row_major);
        __syncwarp();
        int r = lane >> 1, c8 = (lane & 1) * 8;
        int gr = rowBase + rowTile * 16 + r;
        int gc = (colTile0 + t) * 16 + c8;
        const float* p = &os[r * 16 + c8];
        if (gr < N_NODES) {
            __half2* dst = (__half2*)&g_hh[gr * HID + gc];
#pragma unroll
            for (int q = 0; q < 4; ++q)
                dst[q] = __float22half2_rn(make_float2(p[2 * q], p[2 * q + 1]));
        }
        // fused attention-dot partials (8 cols each)
        float ps = 0.f, pd = 0.f;
#pragma unroll
        for (int q = 0; q < 8; ++q) { ps += p[q] * Asm[gc + q]; pd += p[q] * Adm[gc + q]; }
        atomicAdd(&s_as[rowTile * 16 + r], ps);
        atomicAdd(&s_ad[rowTile * 16 + r], pd);
        __syncwarp();
    }
    __syncthreads();
    if (warp == 0) {
        float m = -1e30f;
#pragma unroll
        for (int it = 0; it < 2; ++it) {
            int rr = it * 32 + lane;
            int gr = rowBase + rr;
            if (gr < N_NODES) {
                float s1 = s_as[rr];
                g_as[gr] = s1;
                g_ad[gr] = s_ad[rr];
                m = fmaxf(m, s1);
            }
        }
#pragma unroll
        for (int o = 16; o; o >>= 1) m = fmaxf(m, __shfl_xor_sync(0xffffffffu, m, o));
        if (lane == 0) atomicMax(&g_maxas[1], enc_f(m));
    }
}

// ---------------- fused softmax-aggregation, F=128 (warp per node, fp16 gather) ----
// single edge pass: shift = leaky(global_max(as) + ad_i) >= all e_ij (softmax invariant)
__global__ void k_agg128(const float* __restrict__ b, int layer) {
    int warp = threadIdx.x >> 5, lane = threadIdx.x & 31;
    int i = blockIdx.x * 8 + warp;
    if (i >= N_NODES) return;
    int start = g_off[i], end = g_off[i + 1];
    float adi = g_ad[i];
    float m = leaky(dec_f(g_maxas[layer]) + adi);
    float4 acc = {0.f, 0.f, 0.f, 0.f};
    float denom = 0.f;
    const uint2* hh = (const uint2*)g_hh;
    int j = start;
    for (; j + 4 <= end; j += 4) {
        int s0 = g_ssrc[j], s1 = g_ssrc[j + 1], s2 = g_ssrc[j + 2], s3 = g_ssrc[j + 3];
        float e0 = g_as[s0] + adi, e1 = g_as[s1] + adi,
              e2 = g_as[s2] + adi, e3 = g_as[s3] + adi;
        uint2 p0 = hh[s0 * 32 + lane], p1 = hh[s1 * 32 + lane],
              p2 = hh[s2 * 32 + lane], p3 = hh[s3 * 32 + lane];
        float x0 = __expf(leaky(e0) - m), x1 = __expf(leaky(e1) - m),
              x2 = __expf(leaky(e2) - m), x3 = __expf(leaky(e3) - m);
        denom += (x0 + x1) + (x2 + x3);
        float4 h0 = unpack_half4(p0), h1 = unpack_half4(p1),
               h2 = unpack_half4(p2), h3 = unpack_half4(p3);
        acc.x += x0 * h0.x + x1 * h1.x + x2 * h2.x + x3 * h3.x;
        acc.y += x0 * h0.y + x1 * h1.y + x2 * h2.y + x3 * h3.y;
        acc.z += x0 * h0.z + x1 * h1.z + x2 * h2.z + x3 * h3.z;
        acc.w += x0 * h0.w + x1 * h1.w + x2 * h2.w + x3 * h3.w;
    }
    for (; j < end; ++j) {
        int s = g_ssrc[j];
        float ex = __expf(leaky(g_as[s] + adi) - m);
        denom += ex;
        float4 hv = unpack_half4(hh[s * 32 + lane]);
        acc.x += ex * hv.x; acc.y += ex * hv.y;
        acc.z += ex * hv.z; acc.w += ex * hv.w;
    }
    float inv = 1.f / (denom + 1e-16f);
    float4 bv = ((const float4*)b)[lane];
    float4 r;
    r.x = fmaxf(acc.x * inv + bv.x, 0.f); r.y = fmaxf(acc.y * inv + bv.y, 0.f);
    r.z = fmaxf(acc.z * inv + bv.z, 0.f); r.w = fmaxf(acc.w * inv + bv.w, 0.f);
    ((uint2*)g_feath)[i * 32 + lane] = pack_half4(r.x, r.y, r.z, r.w);
}

// ---------------- layer 3 GEMM (K=128 -> 5, fp16 input) + dots + block max --------
__global__ void k_gemm3(const float* __restrict__ W3,
                        const float* __restrict__ a_src, const float* __restrict__ a_dst) {
    __shared__ float Ws[HID * OUTD];
    __shared__ float As[OUTD], Ad[OUTD];
    __shared__ float smax[8];
    for (int i = threadIdx.x; i < HID * OUTD; i += blockDim.x) Ws[i] = W3[i];
    if (threadIdx.x < OUTD) { As[threadIdx.x] = a_src[threadIdx.x]; Ad[threadIdx.x] = a_dst[threadIdx.x]; }
    __syncthreads();
    int warp = threadIdx.x >> 5, lane = threadIdx.x & 31;
    int node = blockIdx.x * 8 + warp;     // exact grid
    float4 f = unpack_half4(((const uint2*)g_feath)[node * 32 + lane]);
    int k0 = lane * 4;
    float hc[OUTD];
#pragma unroll
    for (int c = 0; c < OUTD; ++c) {
        float s = f.x * Ws[(k0 + 0) * OUTD + c] + f.y * Ws[(k0 + 1) * OUTD + c]
                + f.z * Ws[(k0 + 2) * OUTD + c] + f.w * Ws[(k0 + 3) * OUTD + c];
#pragma unroll
        for (int o = 16; o; o >>= 1) s += __shfl_xor_sync(0xffffffffu, s, o);
        hc[c] = s;
    }
    float s1 = 0.f;
    if (lane == 0) {
        float s2 = 0.f;
#pragma unroll
        for (int c = 0; c < OUTD; ++c) {
            g_h5[node * OUTD + c] = hc[c];
            s1 += hc[c] * As[c];
            s2 += hc[c] * Ad[c];
        }
        g_as[node] = s1; g_ad[node] = s2;
    }
    block_atomic_max(&g_maxas[2], s1, warp, lane, smax);
}

// ---------------- fused aggregation F=5 + bias + log_softmax (warp per node) -------
__global__ void k_agg5(const float* __restrict__ b3, float* __restrict__ out) {
    int warp = threadIdx.x >> 5, lane = threadIdx.x & 31;
    int i = blockIdx.x * 8 + warp;
    if (i >= N_NODES) return;
    int start = g_off[i], end = g_off[i + 1];
    float adi = g_ad[i];
    float m = leaky(dec_f(g_maxas[2]) + adi);
    float a0 = 0.f, a1 = 0.f, a2 = 0.f, a3 = 0.f, a4 = 0.f, denom = 0.f;
    for (int j = start + lane; j < end; j += 32) {
        int s = g_ssrc[j];
        float ex = __expf(leaky(g_as[s] + adi) - m);
        denom += ex;
        const float* hp = &g_h5[s * OUTD];
        a0 += ex * hp[0]; a1 += ex * hp[1]; a2 += ex * hp[2];
        a3 += ex * hp[3]; a4 += ex * hp[4];
    }
#pragma unroll
    for (int o = 16; o; o >>= 1) {
        denom += __shfl_xor_sync(0xffffffffu, denom, o);
        a0 += __shfl_xor_sync(0xffffffffu, a0, o);
        a1 += __shfl_xor_sync(0xffffffffu, a1, o);
        a2 += __shfl_xor_sync(0xffffffffu, a2, o);
        a3 += __shfl_xor_sync(0xffffffffu, a3, o);
        a4 += __shfl_xor_sync(0xffffffffu, a4, o);
    }
    if (lane == 0) {
        float inv = 1.f / (denom + 1e-16f);
        float v[OUTD] = {a0 * inv + b3[0], a1 * inv + b3[1], a2 * inv + b3[2],
                         a3 * inv + b3[3], a4 * inv + b3[4]};
        float mx = -1e30f;
#pragma unroll
        for (int c = 0; c < OUTD; ++c) mx = fmaxf(mx, v[c]);
        float se = 0.f;
#pragma unroll
        for (int c = 0; c < OUTD; ++c) se += __expf(v[c] - mx);
        float lse = mx + logf(se);
#pragma unroll
        for (int c = 0; c < OUTD; ++c) out[i * OUTD + c] = v[c] - lse;
    }
}

// ---------------- launch ----------------
extern "C" void kernel_launch(void* const* d_in, const int* in_sizes, int n_in,
                              void* d_out, int out_size) {
    const float* x   = (const float*)d_in[0];
    const int*   ei  = (const int*)d_in[1];       // int32: JAX x64 is disabled
    const float* W1  = (const float*)d_in[2];
    const float* as1 = (const float*)d_in[3];
    const float* ad1 = (const float*)d_in[4];
    const float* b1  = (const float*)d_in[5];
    const float* W2  = (const float*)d_in[6];
    const float* as2 = (const float*)d_in[7];
    const float* ad2 = (const float*)d_in[8];
    const float* b2  = (const float*)d_in[9];
    const float* W3  = (const float*)d_in[10];
    const float* as3 = (const float*)d_in[11];
    const float* ad3 = (const float*)d_in[12];
    const float* b3  = (const float*)d_in[13];
    float* out = (float*)d_out;

    // CSR build (rebuilt every call — no caching)
    k_init<<<(N_NODES + 255) / 256, 256>>>(W2);
    k_hist<<<(N_EDGES / 4 + 255) / 256, 256>>>(ei);
    k_offsets<<<NBLK, SCAN_BS>>>();
    k_fill<<<(N_EDGES / 4 + 255) / 256, 256>>>(ei);

    int nwb = N_NODES / 8;   // 6250, exact — warp-per-node grids

    // layer 1
    k_gemm1<<<nwb, 256>>>(x, W1, as1, ad1);
    k_agg128<<<nwb, 256>>>(b1, 0);
    // layer 2 (rowdot fused into GEMM epilogue)
    k_gemm2_wmma<<<(N_NODES + 63) / 64, 256>>>(as2, ad2);
    k_agg128<<<nwb, 256>>>(b2, 1);
    // layer 3
    k_gemm3<<<nwb, 256>>>(W3, as3, ad3);
    k_agg5<<<nwb, 256>>>(b3, out);
}

// round 15
// speedup vs baseline: 1.2679x; 1.0003x over previous
#include <cuda_runtime.h>
#include <cuda_fp16.h>
#include <mma.h>
#include <math.h>

using namespace nvcuda;

#define N_NODES 50000
#define N_EDGES 1600000
#define E_TOT   (N_EDGES + N_NODES)
#define HID     128
#define IND     13
#define OUTD    5
#define SCAN_BS 512
#define NBLK    ((N_NODES + SCAN_BS - 1) / SCAN_BS)   // 98

// ---------------- scratch (static device globals; no allocation) ----------------
__device__ int      g_ssrc[E_TOT];           // CSR-sorted source indices (by dst)
__device__ int      g_rank[N_EDGES];         // rank of edge within its dst bucket
__device__ int      g_cnt[N_NODES];
__device__ int      g_off[N_NODES + 1];
__device__ unsigned g_maxas[3];              // per-layer global max of a_src·h (encoded)
__device__ __align__(16) __half g_hh[N_NODES * HID];    // transformed features, fp16
__device__ __align__(16) __half g_feath[N_NODES * HID]; // layer input, fp16
__device__ __align__(16) __half g_W2h[HID * HID];       // W2 in fp16
__device__ float    g_as[N_NODES];
__device__ float    g_ad[N_NODES];
__device__ float    g_h5[N_NODES * OUTD];

// order-preserving float<->uint encoding (atomicMax-able, order-invariant => deterministic)
__device__ __forceinline__ unsigned enc_f(float f) {
    unsigned u = __float_as_uint(f);
    return (u >> 31) ? ~u : (u | 0x80000000u);
}
__device__ __forceinline__ float dec_f(unsigned e) {
    return __uint_as_float((e >> 31) ? (e ^ 0x80000000u) : ~e);
}
__device__ __forceinline__ float leaky(float e) { return e > 0.f ? e : 0.2f * e; }

// block-level (8 warps) max reduce then ONE atomic per block
__device__ __forceinline__ void block_atomic_max(unsigned* dst, float s1, int warp, int lane,
                                                 float* smax) {
    if (lane == 0) smax[warp] = s1;
    __syncthreads();
    if (threadIdx.x == 0) {
        float m = smax[0];
#pragma unroll
        for (int w = 1; w < 8; ++w) m = fmaxf(m, smax[w]);
        atomicMax(dst, enc_f(m));
    }
}

// ---------------- init: cnt=0 + W2->fp16 + maxas ----------
__global__ void k_init(const float* __restrict__ W2) {
    int i = blockIdx.x * blockDim.x + threadIdx.x;
    if (i < N_NODES) g_cnt[i] = 0;
    if (i < HID * HID) g_W2h[i] = __float2half(W2[i]);
    if (i < 3) g_maxas[i] = 0u;
}

// ---------------- CSR build ----------------
// hist: 8 edges/thread — count per dst AND record each edge's bucket rank
__global__ void k_hist(const int* __restrict__ ei) {
    int e8 = blockIdx.x * blockDim.x + threadIdx.x;
    if (e8 >= N_EDGES / 8) return;
    const int4* dp = (const int4*)(ei + N_EDGES);      // dst half (int32: JAX x64 disabled)
    int4 da = dp[2 * e8], db = dp[2 * e8 + 1];
    int4 ra, rb;
    ra.x = atomicAdd(&g_cnt[da.x], 1);
    ra.y = atomicAdd(&g_cnt[da.y], 1);
    ra.z = atomicAdd(&g_cnt[da.z], 1);
    ra.w = atomicAdd(&g_cnt[da.w], 1);
    rb.x = atomicAdd(&g_cnt[db.x], 1);
    rb.y = atomicAdd(&g_cnt[db.y], 1);
    rb.z = atomicAdd(&g_cnt[db.z], 1);
    rb.w = atomicAdd(&g_cnt[db.w], 1);
    ((int4*)g_rank)[2 * e8]     = ra;
    ((int4*)g_rank)[2 * e8 + 1] = rb;
}

// offsets: block prefix via strided sum (+1 per node for self-loop) + intra-block scan.
// Also places each node's self-loop at slot off[i] (bucket position 0).
__global__ void k_offsets() {
    __shared__ int sm[SCAN_BS];
    int t = threadIdx.x;
    int base = blockIdx.x * SCAN_BS;
    int pre = 0;
    for (int i = t; i < base; i += SCAN_BS) pre += g_cnt[i];
    sm[t] = pre;
    __syncthreads();
    for (int o = SCAN_BS / 2; o > 0; o >>= 1) {
        if (t < o) sm[t] += sm[t + o];
        __syncthreads();
    }
    int blockpre = sm[0] + base;            // +1 self-loop for each preceding node
    __syncthreads();
    int i = base + t;
    int v = (i < N_NODES) ? g_cnt[i] + 1 : 0;   // +1 = self-loop
    sm[t] = v;
    __syncthreads();
    for (int o = 1; o < SCAN_BS; o <<= 1) {
        int u = (t >= o) ? sm[t - o] : 0;
        __syncthreads();
        sm[t] += u;
        __syncthreads();
    }
    if (i < N_NODES) {
        int excl = sm[t] - v + blockpre;
        g_off[i] = excl;
        g_ssrc[excl] = i;                   // self-loop occupies bucket slot 0
        if (i == N_NODES - 1) g_off[N_NODES] = excl + v;   // == E_TOT
    }
}

// fill: atomic-free scatter, 8 edges/thread — pos = off[dst] + 1 + rank
__global__ void k_fill(const int* __restrict__ ei) {
    int e8 = blockIdx.x * blockDim.x + threadIdx.x;
    if (e8 >= N_EDGES / 8) return;
    const int4* sp = (const int4*)ei;
    const int4* dp = (const int4*)(ei + N_EDGES);
    const int4* rp = (const int4*)g_rank;
    int4 sa = sp[2 * e8], sb = sp[2 * e8 + 1];
    int4 da = dp[2 * e8], db = dp[2 * e8 + 1];
    int4 ra = rp[2 * e8], rb = rp[2 * e8 + 1];
    int oa0 = g_off[da.x], oa1 = g_off[da.y], oa2 = g_off[da.z], oa3 = g_off[da.w];
    int ob0 = g_off[db.x], ob1 = g_off[db.y], ob2 = g_off[db.z], ob3 = g_off[db.w];
    g_ssrc[oa0 + 1 + ra.x] = sa.x;
    g_ssrc[oa1 + 1 + ra.y] = sa.y;
    g_ssrc[oa2 + 1 + ra.z] = sa.z;
    g_ssrc[oa3 + 1 + ra.w] = sa.w;
    g_ssrc[ob0 + 1 + rb.x] = sb.x;
    g_ssrc[ob1 + 1 + rb.y] = sb.y;
    g_ssrc[ob2 + 1 + rb.z] = sb.z;
    g_ssrc[ob3 + 1 + rb.w] = sb.w;
}

// ---------------- helpers ----------------
__device__ __forceinline__ uint2 pack_half4(float a, float b, float c, float d) {
    __half2 h0 = __float22half2_rn(make_float2(a, b));
    __half2 h1 = __float22half2_rn(make_float2(c, d));
    uint2 u;
    u.x = *reinterpret_cast<unsigned*>(&h0);
    u.y = *reinterpret_cast<unsigned*>(&h1);
    return u;
}
__device__ __forceinline__ float4 unpack_half4(uint2 u) {
    __half2 h0 = *reinterpret_cast<__half2*>(&u.x);
    __half2 h1 = *reinterpret_cast<__half2*>(&u.y);
    float2 f0 = __half22float2(h0), f1 = __half22float2(h1);
    return make_float4(f0.x, f0.y, f1.x, f1.y);
}

// ---------------- layer 1 GEMM (K=13) + fused attention dots + block-reduced max --
__global__ void k_gemm1(const float* __restrict__ x, const float* __restrict__ W1,
                        const float* __restrict__ a_src, const float* __restrict__ a_dst) {
    __shared__ __align__(16) float Ws[IND * HID];
    __shared__ __align__(16) float As[HID];
    __shared__ __align__(16) float Ad[HID];
    __shared__ float smax[8];
    for (int i = threadIdx.x; i < IND * HID; i += blockDim.x) Ws[i] = W1[i];
    for (int i = threadIdx.x; i < HID; i += blockDim.x) { As[i] = a_src[i]; Ad[i] = a_dst[i]; }
    __syncthreads();
    int warp = threadIdx.x >> 5, lane = threadIdx.x & 31;
    int node = blockIdx.x * 8 + warp;     // exact: 50000 = 6250*8
    float xv[IND];
#pragma unroll
    for (int k = 0; k < IND; ++k) xv[k] = x[node * IND + k];
    float4 acc = {0.f, 0.f, 0.f, 0.f};
#pragma unroll
    for (int k = 0; k < IND; ++k) {
        float4 w = *(const float4*)&Ws[k * HID + lane * 4];
        acc.x += xv[k] * w.x; acc.y += xv[k] * w.y;
        acc.z += xv[k] * w.z; acc.w += xv[k] * w.w;
    }
    ((uint2*)g_hh)[node * 32 + lane] = pack_half4(acc.x, acc.y, acc.z, acc.w);
    float4 a1 = *(const float4*)&As[lane * 4];
    float4 a2 = *(const float4*)&Ad[lane * 4];
    float s1 = acc.x * a1.x + acc.y * a1.y + acc.z * a1.z + acc.w * a1.w;
    float s2 = acc.x * a2.x + acc.y * a2.y + acc.z * a2.z + acc.w * a2.w;
#pragma unroll
    for (int o = 16; o; o >>= 1) {
        s1 += __shfl_xor_sync(0xffffffffu, s1, o);
        s2 += __shfl_xor_sync(0xffffffffu, s2, o);
    }
    if (lane == 0) { g_as[node] = s1; g_ad[node] = s2; }
    block_atomic_max(&g_maxas[0], s1, warp, lane, smax);
}

// ---------------- layer 2 GEMM via WMMA + fused attention dots -------------------
// block 256 (8 warps), 64 rows x 128 cols. Warp w: row-tile w>>1, col-tiles (w&1)*4..+3.
#define FS_LD 136
__global__ void k_gemm2_wmma(const float* __restrict__ a_src, const float* __restrict__ a_dst) {
    __shared__ __align__(16) __half Fs[64 * FS_LD];
    __shared__ __align__(16) float  Os[8 * 256];       // per-warp 16x16 staging
    __shared__ float Asm[HID], Adm[HID];
    __shared__ float s_as[64], s_ad[64];
    int rowBase = blockIdx.x * 64;
    int warp = threadIdx.x >> 5, lane = threadIdx.x & 31;
    if (threadIdx.x < HID) { Asm[threadIdx.x] = a_src[threadIdx.x]; Adm[threadIdx.x] = a_dst[threadIdx.x]; }
    if (threadIdx.x < 64) { s_as[threadIdx.x] = 0.f; s_ad[threadIdx.x] = 0.f; }
    for (int v = threadIdx.x * 8; v < 64 * HID; v += 256 * 8) {
        int r = v >> 7, c = v & 127;
        int gr = rowBase + r;
        uint4 d = (gr < N_NODES) ? *(const uint4*)&g_feath[gr * HID + c]
                                 : make_uint4(0u, 0u, 0u, 0u);
        *(uint4*)&Fs[r * FS_LD + c] = d;
    }
    __syncthreads();
    int rowTile = warp >> 1;
    int colTile0 = (warp & 1) * 4;
    wmma::fragment<wmma::accumulator, 16, 16, 16, float> acc[4];
#pragma unroll
    for (int t = 0; t < 4; ++t) wmma::fill_fragment(acc[t], 0.f);
    for (int k = 0; k < HID; k += 16) {
        wmma::fragment<wmma::matrix_a, 16, 16, 16, __half, wmma::row_major> a;
        wmma::load_matrix_sync(a, &Fs[rowTile * 16 * FS_LD + k], FS_LD);
#pragma unroll
        for (int t = 0; t < 4; ++t) {
            wmma::fragment<wmma::matrix_b, 16, 16, 16, __half, wmma::row_major> b;
            wmma::load_matrix_sync(b, &g_W2h[k * HID + (colTile0 + t) * 16], HID);
            wmma::mma_sync(acc[t], a, b, acc[t]);
        }
    }
    float* os = &Os[warp * 256];
#pragma unroll
    for (int t = 0; t < 4; ++t) {
        wmma::store_matrix_sync(os, acc[t], 16, wmma::mem_row_major);
        __syncwarp();
        int r = lane >> 1, c8 = (lane & 1) * 8;
        int gr = rowBase + rowTile * 16 + r;
        int gc = (colTile0 + t) * 16 + c8;
        const float* p = &os[r * 16 + c8];
        if (gr < N_NODES) {
            __half2* dst = (__half2*)&g_hh[gr * HID + gc];
#pragma unroll
            for (int q = 0; q < 4; ++q)
                dst[q] = __float22half2_rn(make_float2(p[2 * q], p[2 * q + 1]));
        }
        // fused attention-dot partials (8 cols each)
        float ps = 0.f, pd = 0.f;
#pragma unroll
        for (int q = 0; q < 8; ++q) { ps += p[q] * Asm[gc + q]; pd += p[q] * Adm[gc + q]; }
        atomicAdd(&s_as[rowTile * 16 + r], ps);
        atomicAdd(&s_ad[rowTile * 16 + r], pd);
        __syncwarp();
    }
    __syncthreads();
    if (warp == 0) {
        float m = -1e30f;
#pragma unroll
        for (int it = 0; it < 2; ++it) {
            int rr = it * 32 + lane;
            int gr = rowBase + rr;
            if (gr < N_NODES) {
                float s1 = s_as[rr];
                g_as[gr] = s1;
                g_ad[gr] = s_ad[rr];
                m = fmaxf(m, s1);
            }
        }
#pragma unroll
        for (int o = 16; o; o >>= 1) m = fmaxf(m, __shfl_xor_sync(0xffffffffu, m, o));
        if (lane == 0) atomicMax(&g_maxas[1], enc_f(m));
    }
}

// ---------------- fused softmax-aggregation, F=128 (warp per node, fp16 gather) ----
// single edge pass: shift = leaky(global_max(as) + ad_i) >= all e_ij (softmax invariant)
__global__ void k_agg128(const float* __restrict__ b, int layer) {
    int warp = threadIdx.x >> 5, lane = threadIdx.x & 31;
    int i = blockIdx.x * 8 + warp;
    if (i >= N_NODES) return;
    int start = g_off[i], end = g_off[i + 1];
    float adi = g_ad[i];
    float m = leaky(dec_f(g_maxas[layer]) + adi);
    float4 acc = {0.f, 0.f, 0.f, 0.f};
    float denom = 0.f;
    const uint2* hh = (const uint2*)g_hh;
    int j = start;
    for (; j + 8 <= end; j += 8) {
        int s0 = g_ssrc[j],     s1 = g_ssrc[j + 1], s2 = g_ssrc[j + 2], s3 = g_ssrc[j + 3];
        int s4 = g_ssrc[j + 4], s5 = g_ssrc[j + 5], s6 = g_ssrc[j + 6], s7 = g_ssrc[j + 7];
        float e0 = g_as[s0], e1 = g_as[s1], e2 = g_as[s2], e3 = g_as[s3];
        float e4 = g_as[s4], e5 = g_as[s5], e6 = g_as[s6], e7 = g_as[s7];
        uint2 p0 = hh[s0 * 32 + lane], p1 = hh[s1 * 32 + lane],
              p2 = hh[s2 * 32 + lane], p3 = hh[s3 * 32 + lane],
              p4 = hh[s4 * 32 + lane], p5 = hh[s5 * 32 + lane],
              p6 = hh[s6 * 32 + lane], p7 = hh[s7 * 32 + lane];
        float x0 = __expf(leaky(e0 + adi) - m), x1 = __expf(leaky(e1 + adi) - m),
              x2 = __expf(leaky(e2 + adi) - m), x3 = __expf(leaky(e3 + adi) - m),
              x4 = __expf(leaky(e4 + adi) - m), x5 = __expf(leaky(e5 + adi) - m),
              x6 = __expf(leaky(e6 + adi) - m), x7 = __expf(leaky(e7 + adi) - m);
        denom += ((x0 + x1) + (x2 + x3)) + ((x4 + x5) + (x6 + x7));
        float4 h0 = unpack_half4(p0), h1 = unpack_half4(p1),
               h2 = unpack_half4(p2), h3 = unpack_half4(p3),
               h4 = unpack_half4(p4), h5 = unpack_half4(p5),
               h6 = unpack_half4(p6), h7 = unpack_half4(p7);
        acc.x += (x0 * h0.x + x1 * h1.x + x2 * h2.x + x3 * h3.x)
               + (x4 * h4.x + x5 * h5.x + x6 * h6.x + x7 * h7.x);
        acc.y += (x0 * h0.y + x1 * h1.y + x2 * h2.y + x3 * h3.y)
               + (x4 * h4.y + x5 * h5.y + x6 * h6.y + x7 * h7.y);
        acc.z += (x0 * h0.z + x1 * h1.z + x2 * h2.z + x3 * h3.z)
               + (x4 * h4.z + x5 * h5.z + x6 * h6.z + x7 * h7.z);
        acc.w += (x0 * h0.w + x1 * h1.w + x2 * h2.w + x3 * h3.w)
               + (x4 * h4.w + x5 * h5.w + x6 * h6.w + x7 * h7.w);
    }
    for (; j < end; ++j) {
        int s = g_ssrc[j];
        float ex = __expf(leaky(g_as[s] + adi) - m);
        denom += ex;
        float4 hv = unpack_half4(hh[s * 32 + lane]);
        acc.x += ex * hv.x; acc.y += ex * hv.y;
        acc.z += ex * hv.z; acc.w += ex * hv.w;
    }
    float inv = 1.f / (denom + 1e-16f);
    float4 bv = ((const float4*)b)[lane];
    float4 r;
    r.x = fmaxf(acc.x * inv + bv.x, 0.f); r.y = fmaxf(acc.y * inv + bv.y, 0.f);
    r.z = fmaxf(acc.z * inv + bv.z, 0.f); r.w = fmaxf(acc.w * inv + bv.w, 0.f);
    ((uint2*)g_feath)[i * 32 + lane] = pack_half4(r.x, r.y, r.z, r.w);
}

// ---------------- layer 3 GEMM (K=128 -> 5, fp16 input) + dots + block max --------
__global__ void k_gemm3(const float* __restrict__ W3,
                        const float* __restrict__ a_src, const float* __restrict__ a_dst) {
    __shared__ float Ws[HID * OUTD];
    __shared__ float As[OUTD], Ad[OUTD];
    __shared__ float smax[8];
    for (int i = threadIdx.x; i < HID * OUTD; i += blockDim.x) Ws[i] = W3[i];
    if (threadIdx.x < OUTD) { As[threadIdx.x] = a_src[threadIdx.x]; Ad[threadIdx.x] = a_dst[threadIdx.x]; }
    __syncthreads();
    int warp = threadIdx.x >> 5, lane = threadIdx.x & 31;
    int node = blockIdx.x * 8 + warp;     // exact grid
    float4 f = unpack_half4(((const uint2*)g_feath)[node * 32 + lane]);
    int k0 = lane * 4;
    float hc[OUTD];
#pragma unroll
    for (int c = 0; c < OUTD; ++c) {
        float s = f.x * Ws[(k0 + 0) * OUTD + c] + f.y * Ws[(k0 + 1) * OUTD + c]
                + f.z * Ws[(k0 + 2) * OUTD + c] + f.w * Ws[(k0 + 3) * OUTD + c];
#pragma unroll
        for (int o = 16; o; o >>= 1) s += __shfl_xor_sync(0xffffffffu, s, o);
        hc[c] = s;
    }
    float s1 = 0.f;
    if (lane == 0) {
        float s2 = 0.f;
#pragma unroll
        for (int c = 0; c < OUTD; ++c) {
            g_h5[node * OUTD + c] = hc[c];
            s1 += hc[c] * As[c];
            s2 += hc[c] * Ad[c];
        }
        g_as[node] = s1; g_ad[node] = s2;
    }
    block_atomic_max(&g_maxas[2], s1, warp, lane, smax);
}

// ---------------- fused aggregation F=5 + bias + log_softmax (warp per node) -------
__global__ void k_agg5(const float* __restrict__ b3, float* __restrict__ out) {
    int warp = threadIdx.x >> 5, lane = threadIdx.x & 31;
    int i = blockIdx.x * 8 + warp;
    if (i >= N_NODES) return;
    int start = g_off[i], end = g_off[i + 1];
    float adi = g_ad[i];
    float m = leaky(dec_f(g_maxas[2]) + adi);
    float a0 = 0.f, a1 = 0.f, a2 = 0.f, a3 = 0.f, a4 = 0.f, denom = 0.f;
    for (int j = start + lane; j < end; j += 32) {
        int s = g_ssrc[j];
        float ex = __expf(leaky(g_as[s] + adi) - m);
        denom += ex;
        const float* hp = &g_h5[s * OUTD];
        a0 += ex * hp[0]; a1 += ex * hp[1]; a2 += ex * hp[2];
        a3 += ex * hp[3]; a4 += ex * hp[4];
    }
#pragma unroll
    for (int o = 16; o; o >>= 1) {
        denom += __shfl_xor_sync(0xffffffffu, denom, o);
        a0 += __shfl_xor_sync(0xffffffffu, a0, o);
        a1 += __shfl_xor_sync(0xffffffffu, a1, o);
        a2 += __shfl_xor_sync(0xffffffffu, a2, o);
        a3 += __shfl_xor_sync(0xffffffffu, a3, o);
        a4 += __shfl_xor_sync(0xffffffffu, a4, o);
    }
    if (lane == 0) {
        float inv = 1.f / (denom + 1e-16f);
        float v[OUTD] = {a0 * inv + b3[0], a1 * inv + b3[1], a2 * inv + b3[2],
                         a3 * inv + b3[3], a4 * inv + b3[4]};
        float mx = -1e30f;
#pragma unroll
        for (int c = 0; c < OUTD; ++c) mx = fmaxf(mx, v[c]);
        float se = 0.f;
#pragma unroll
        for (int c = 0; c < OUTD; ++c) se += __expf(v[c] - mx);
        float lse = mx + logf(se);
#pragma unroll
        for (int c = 0; c < OUTD; ++c) out[i * OUTD + c] = v[c] - lse;
    }
}

// ---------------- launch ----------------
extern "C" void kernel_launch(void* const* d_in, const int* in_sizes, int n_in,
                              void* d_out, int out_size) {
    const float* x   = (const float*)d_in[0];
    const int*   ei  = (const int*)d_in[1];       // int32: JAX x64 is disabled
    const float* W1  = (const float*)d_in[2];
    const float* as1 = (const float*)d_in[3];
    const float* ad1 = (const float*)d_in[4];
    const float* b1  = (const float*)d_in[5];
    const float* W2  = (const float*)d_in[6];
    const float* as2 = (const float*)d_in[7];
    const float* ad2 = (const float*)d_in[8];
    const float* b2  = (const float*)d_in[9];
    const float* W3  = (const float*)d_in[10];
    const float* as3 = (const float*)d_in[11];
    const float* ad3 = (const float*)d_in[12];
    const float* b3  = (const float*)d_in[13];
    float* out = (float*)d_out;

    // CSR build (rebuilt every call — no caching)
    k_init<<<(N_NODES + 255) / 256, 256>>>(W2);
    k_hist<<<(N_EDGES / 8 + 255) / 256, 256>>>(ei);
    k_offsets<<<NBLK, SCAN_BS>>>();
    k_fill<<<(N_EDGES / 8 + 255) / 256, 256>>>(ei);

    int nwb = N_NODES / 8;   // 6250, exact — warp-per-node grids

    // layer 1
    k_gemm1<<<nwb, 256>>>(x, W1, as1, ad1);
    k_agg128<<<nwb, 256>>>(b1, 0);
    // layer 2 (rowdot fused into GEMM epilogue)
    k_gemm2_wmma<<<(N_NODES + 63) / 64, 256>>>(as2, ad2);
    k_agg128<<<nwb, 256>>>(b2, 1);
    // layer 3
    k_gemm3<<<nwb, 256>>>(W3, as3, ad3);
    k_agg5<<<nwb, 256>>>(b3, out);
}